// round 11
// baseline (speedup 1.0000x reference)
#include <cuda_runtime.h>
#include <math_constants.h>

// ---------------- problem constants ----------------
constexpr int   kD     = 2048;
constexpr int   kF     = 2048;
constexpr int   kE     = 8;
constexpr int   kT     = 4096;       // tokens = 4*1024
constexpr int   kSlots = 2 * kT;     // top-2 assignments
constexpr int   kBM    = 64;
constexpr float kAlpha = 1.702f;
constexpr float kLimit = 7.0f;
constexpr float kAux   = 0.01f;

// ---------------- device scratch (no allocations allowed) ----------------
__device__ int   g_counts[kE];
__device__ int   g_sid[kE * kT];                 // slot id = token*2 + k
__device__ float g_sw [kE * kT];                 // routing weight for slot
__device__ float g_probs[kT * kE];               // full softmax probs
__device__ float g_act[(size_t)kSlots * kF];     // 64 MB: activated hidden
__device__ float g_partial[(size_t)kSlots * kD]; // 64 MB: weighted expert out

// ---------------- kernel 0: reset counters (graph replays!) --------------
__global__ void moe_init_kernel() {
    if (threadIdx.x < kE) g_counts[threadIdx.x] = 0;
}

// ---------------- kernel 1: router (one warp per token) ------------------
__global__ void moe_router_kernel(const float* __restrict__ x,
                                  const float* __restrict__ rw,
                                  const float* __restrict__ rb) {
    int gw   = (blockIdx.x * blockDim.x + threadIdx.x) >> 5;
    int lane = threadIdx.x & 31;
    if (gw >= kT) return;

    const float* xr = x + (size_t)gw * kD;
    float acc[kE];
#pragma unroll
    for (int e = 0; e < kE; ++e) acc[e] = 0.f;

    for (int d = lane; d < kD; d += 32) {
        float xv = xr[d];
        const float* w = rw + (size_t)d * kE;
#pragma unroll
        for (int e = 0; e < kE; ++e) acc[e] = fmaf(xv, w[e], acc[e]);
    }
#pragma unroll
    for (int e = 0; e < kE; ++e) {
#pragma unroll
        for (int off = 16; off > 0; off >>= 1)
            acc[e] += __shfl_xor_sync(0xffffffffu, acc[e], off);
    }

    if (lane == 0) {
        float lg[kE];
#pragma unroll
        for (int e = 0; e < kE; ++e) lg[e] = acc[e] + rb[e];

        // top-2 (ties -> lowest index, matching lax.top_k)
        int i0 = 0; float l0 = lg[0];
#pragma unroll
        for (int e = 1; e < kE; ++e) if (lg[e] > l0) { l0 = lg[e]; i0 = e; }
        int i1 = -1; float l1 = -CUDART_INF_F;
#pragma unroll
        for (int e = 0; e < kE; ++e)
            if (e != i0 && lg[e] > l1) { l1 = lg[e]; i1 = e; }

        // full softmax probs (needed for aux loss)
        float p[kE]; float s = 0.f;
#pragma unroll
        for (int e = 0; e < kE; ++e) { p[e] = __expf(lg[e] - l0); s += p[e]; }
        float inv = 1.f / s;
#pragma unroll
        for (int e = 0; e < kE; ++e) g_probs[gw * kE + e] = p[e] * inv;

        // routing weights = softmax([l0, l1])
        float r  = __expf(l1 - l0);
        float w0 = 1.f / (1.f + r);
        float w1 = r * w0;

        int s0 = atomicAdd(&g_counts[i0], 1);
        g_sid[i0 * kT + s0] = gw * 2;     g_sw[i0 * kT + s0] = w0;
        int s1 = atomicAdd(&g_counts[i1], 1);
        g_sid[i1 * kT + s1] = gw * 2 + 1; g_sw[i1 * kT + s1] = w1;
    }
}

// ---------------- kernel 2: gathered gate_up GEMM + GLU activation -------
// Tile: 64 rows (assignments) x 64 act-cols (128 weight cols) x K-step 32.
// 256 threads, each owns 4 rows x 4 act-cols (gate+up accumulators).
__global__ void __launch_bounds__(256)
moe_gate_up_kernel(const float* __restrict__ x,
                   const float* __restrict__ wgu,   // [E][D][2F]
                   const float* __restrict__ bgu) { // [E][2F]
    const int e   = blockIdx.y >> 6;
    const int m0  = (blockIdx.y & 63) * kBM;
    const int cnt = g_counts[e];
    if (m0 >= cnt) return;
    const int f0 = blockIdx.x * 64;

    __shared__ __align__(16) float As[32][68];
    __shared__ __align__(16) float Bs[32][128];
    __shared__ int s_sid[kBM];

    const int tid = threadIdx.x;
    if (tid < kBM) {
        int m = m0 + tid;
        s_sid[tid] = (m < cnt) ? g_sid[e * kT + m] : -1;
    }
    __syncthreads();

    // A loader: row = tid&63, k-chunk = (tid>>6)*4 (and +16)
    const int ra = tid & 63;
    const int ka = (tid >> 6) * 4;
    int sidA = s_sid[ra];
    const float* apA = x + (size_t)(sidA < 0 ? 0 : (sidA >> 1)) * kD + ka;

    // B loader: row = (tid>>5) + 8*i, col = (tid&31)*4
    const int rb0 = tid >> 5;
    const int cb  = (tid & 31) * 4;
    const float* bp = wgu + (size_t)e * kD * (2 * kF)
                          + (size_t)rb0 * (2 * kF) + (size_t)f0 * 2 + cb;

    const int ty = tid >> 4;
    const int tx = tid & 15;

    float accg[4][4], accu[4][4];
#pragma unroll
    for (int i = 0; i < 4; ++i)
#pragma unroll
        for (int j = 0; j < 4; ++j) { accg[i][j] = 0.f; accu[i][j] = 0.f; }

    for (int k0 = 0; k0 < kD; k0 += 32) {
        float4 a0 = *(const float4*)(apA + k0);
        float4 a1 = *(const float4*)(apA + k0 + 16);
        float4 b0 = *(const float4*)(bp + (size_t)(k0 +  0) * (2 * kF));
        float4 b1 = *(const float4*)(bp + (size_t)(k0 +  8) * (2 * kF));
        float4 b2 = *(const float4*)(bp + (size_t)(k0 + 16) * (2 * kF));
        float4 b3 = *(const float4*)(bp + (size_t)(k0 + 24) * (2 * kF));
        __syncthreads();
        As[ka + 0][ra] = a0.x; As[ka + 1][ra] = a0.y;
        As[ka + 2][ra] = a0.z; As[ka + 3][ra] = a0.w;
        As[ka + 16][ra] = a1.x; As[ka + 17][ra] = a1.y;
        As[ka + 18][ra] = a1.z; As[ka + 19][ra] = a1.w;
        *(float4*)&Bs[rb0     ][cb] = b0;
        *(float4*)&Bs[rb0 +  8][cb] = b1;
        *(float4*)&Bs[rb0 + 16][cb] = b2;
        *(float4*)&Bs[rb0 + 24][cb] = b3;
        __syncthreads();

#pragma unroll
        for (int kk = 0; kk < 32; ++kk) {
            float4 av  = *(const float4*)&As[kk][ty * 4];
            float4 bv0 = *(const float4*)&Bs[kk][tx * 8];
            float4 bv1 = *(const float4*)&Bs[kk][tx * 8 + 4];
            float a[4]   = {av.x, av.y, av.z, av.w};
            float bgv[4] = {bv0.x, bv0.z, bv1.x, bv1.z};
            float buv[4] = {bv0.y, bv0.w, bv1.y, bv1.w};
#pragma unroll
            for (int i = 0; i < 4; ++i)
#pragma unroll
                for (int j = 0; j < 4; ++j) {
                    accg[i][j] = fmaf(a[i], bgv[j], accg[i][j]);
                    accu[i][j] = fmaf(a[i], buv[j], accu[i][j]);
                }
        }
    }

    // epilogue: bias + clamp + SiLU-GLU, store to act[slot]
#pragma unroll
    for (int i = 0; i < 4; ++i) {
        int r = ty * 4 + i;
        int sid = s_sid[r];
        if (sid < 0) continue;
        float4 o;
        float* ov = (float*)&o;
#pragma unroll
        for (int j = 0; j < 4; ++j) {
            int f = f0 + tx * 4 + j;
            float g = accg[i][j] + bgu[e * (2 * kF) + 2 * f];
            float u = accu[i][j] + bgu[e * (2 * kF) + 2 * f + 1];
            g = fminf(g, kLimit);
            u = fminf(fmaxf(u, -kLimit), kLimit);
            float sig = 1.f / (1.f + __expf(-kAlpha * g));
            ov[j] = (u + 1.f) * (g * sig);
        }
        *(float4*)(g_act + (size_t)sid * kF + f0 + tx * 4) = o;
    }
}

// ---------------- kernel 3: gathered down GEMM (+bias, x routing weight) -
// Tile: 64 rows x 128 out-cols x K-step 32; each thread 4 rows x 8 cols.
__global__ void __launch_bounds__(256)
moe_down_kernel(const float* __restrict__ wdn,   // [E][F][D]
                const float* __restrict__ bdn) { // [E][D]
    const int e   = blockIdx.y >> 6;
    const int m0  = (blockIdx.y & 63) * kBM;
    const int cnt = g_counts[e];
    if (m0 >= cnt) return;
    const int n0 = blockIdx.x * 128;

    __shared__ __align__(16) float As[32][68];
    __shared__ __align__(16) float Bs[32][128];
    __shared__ int   s_sid[kBM];
    __shared__ float s_w[kBM];

    const int tid = threadIdx.x;
    if (tid < kBM) {
        int m = m0 + tid;
        bool v = (m < cnt);
        s_sid[tid] = v ? g_sid[e * kT + m] : -1;
        s_w[tid]   = v ? g_sw [e * kT + m] : 0.f;
    }
    __syncthreads();

    const int ra = tid & 63;
    const int ka = (tid >> 6) * 4;
    int sidA = s_sid[ra];
    const float* apA = g_act + (size_t)(sidA < 0 ? 0 : sidA) * kF + ka;

    const int rb0 = tid >> 5;
    const int cb  = (tid & 31) * 4;
    const float* bp = wdn + (size_t)e * kF * kD + (size_t)rb0 * kD + n0 + cb;

    const int ty = tid >> 4;
    const int tx = tid & 15;

    float acc[4][8];
#pragma unroll
    for (int i = 0; i < 4; ++i)
#pragma unroll
        for (int j = 0; j < 8; ++j) acc[i][j] = 0.f;

    for (int k0 = 0; k0 < kF; k0 += 32) {
        float4 a0 = *(const float4*)(apA + k0);
        float4 a1 = *(const float4*)(apA + k0 + 16);
        float4 b0 = *(const float4*)(bp + (size_t)(k0 +  0) * kD);
        float4 b1 = *(const float4*)(bp + (size_t)(k0 +  8) * kD);
        float4 b2 = *(const float4*)(bp + (size_t)(k0 + 16) * kD);
        float4 b3 = *(const float4*)(bp + (size_t)(k0 + 24) * kD);
        __syncthreads();
        As[ka + 0][ra] = a0.x; As[ka + 1][ra] = a0.y;
        As[ka + 2][ra] = a0.z; As[ka + 3][ra] = a0.w;
        As[ka + 16][ra] = a1.x; As[ka + 17][ra] = a1.y;
        As[ka + 18][ra] = a1.z; As[ka + 19][ra] = a1.w;
        *(float4*)&Bs[rb0     ][cb] = b0;
        *(float4*)&Bs[rb0 +  8][cb] = b1;
        *(float4*)&Bs[rb0 + 16][cb] = b2;
        *(float4*)&Bs[rb0 + 24][cb] = b3;
        __syncthreads();

#pragma unroll
        for (int kk = 0; kk < 32; ++kk) {
            float4 av  = *(const float4*)&As[kk][ty * 4];
            float4 bv0 = *(const float4*)&Bs[kk][tx * 8];
            float4 bv1 = *(const float4*)&Bs[kk][tx * 8 + 4];
            float a[4] = {av.x, av.y, av.z, av.w};
            float b[8] = {bv0.x, bv0.y, bv0.z, bv0.w,
                          bv1.x, bv1.y, bv1.z, bv1.w};
#pragma unroll
            for (int i = 0; i < 4; ++i)
#pragma unroll
                for (int j = 0; j < 8; ++j)
                    acc[i][j] = fmaf(a[i], b[j], acc[i][j]);
        }
    }

#pragma unroll
    for (int i = 0; i < 4; ++i) {
        int r = ty * 4 + i;
        int sid = s_sid[r];
        if (sid < 0) continue;
        float w = s_w[r];
        float4 o0, o1;
        float* ov0 = (float*)&o0;
        float* ov1 = (float*)&o1;
#pragma unroll
        for (int j = 0; j < 4; ++j) {
            int c = n0 + tx * 8 + j;
            ov0[j] = w * (acc[i][j] + bdn[e * kD + c]);
        }
#pragma unroll
        for (int j = 4; j < 8; ++j) {
            int c = n0 + tx * 8 + j;
            ov1[j - 4] = w * (acc[i][j] + bdn[e * kD + c]);
        }
        float* dst = g_partial + (size_t)sid * kD + n0 + tx * 8;
        *(float4*)dst       = o0;
        *(float4*)(dst + 4) = o1;
    }
}

// ---------------- kernel 4: combine the two expert partials per token ----
__global__ void moe_combine_kernel(float* __restrict__ out) {
    size_t idx = (size_t)blockIdx.x * blockDim.x + threadIdx.x; // float4 idx
    // total float4 = kT * kD / 4 = 2,097,152 (grid sized exactly)
    size_t t = idx >> 9;          // / (kD/4)
    size_t c = idx & 511;         // % (kD/4)
    const float4* p = (const float4*)g_partial;
    float4 a = p[(2 * t) * 512 + c];
    float4 b = p[(2 * t + 1) * 512 + c];
    float4 o = make_float4(a.x + b.x, a.y + b.y, a.z + b.z, a.w + b.w);
    ((float4*)out)[idx] = o;
}

// ---------------- kernel 5: expert loads + aux loss (deterministic) ------
__global__ void moe_loss_kernel(float* __restrict__ out_tail) {
    __shared__ float red[256];
    __shared__ float means[kE];
    float s[kE];
#pragma unroll
    for (int e = 0; e < kE; ++e) s[e] = 0.f;
    for (int t = threadIdx.x; t < kT; t += 256) {
        const float* p = g_probs + (size_t)t * kE;
#pragma unroll
        for (int e = 0; e < kE; ++e) s[e] += p[e];
    }
    for (int e = 0; e < kE; ++e) {
        red[threadIdx.x] = s[e];
        __syncthreads();
        for (int off = 128; off > 0; off >>= 1) {
            if (threadIdx.x < off) red[threadIdx.x] += red[threadIdx.x + off];
            __syncthreads();
        }
        if (threadIdx.x == 0) means[e] = red[0] / (float)kT;
        __syncthreads();
    }
    if (threadIdx.x == 0) {
        float loss = 0.f;
        for (int e = 0; e < kE; ++e) {
            float frac = (float)g_counts[e] / (float)(kT * 2);
            out_tail[e] = frac;                 // expert_loads
            loss += frac * means[e];
        }
        out_tail[kE] = kAux * (float)kE * loss; // load_balancing_loss
    }
}

// ---------------- launch ----------------
extern "C" void kernel_launch(void* const* d_in, const int* in_sizes, int n_in,
                              void* d_out, int out_size) {
    const float* x   = (const float*)d_in[0];
    const float* rw  = (const float*)d_in[1];
    const float* rb  = (const float*)d_in[2];
    const float* wgu = (const float*)d_in[3];
    const float* bgu = (const float*)d_in[4];
    const float* wdn = (const float*)d_in[5];
    const float* bdn = (const float*)d_in[6];
    float* out = (float*)d_out;

    moe_init_kernel<<<1, 32>>>();
    moe_router_kernel<<<(kT * 32) / 256, 256>>>(x, rw, rb);

    // worst case: one expert owns all 4096 tokens -> 64 M-tiles per expert
    dim3 g1(kF / 64, kE * 64);   // (32, 512)
    moe_gate_up_kernel<<<g1, 256>>>(x, wgu, bgu);

    dim3 g2(kD / 128, kE * 64);  // (16, 512)
    moe_down_kernel<<<g2, 256>>>(wdn, bdn);

    moe_combine_kernel<<<(kT * kD / 4) / 256, 256>>>(out);
    moe_loss_kernel<<<1, 256>>>(out + (size_t)kT * kD);
}

// round 12
// speedup vs baseline: 1.0001x; 1.0001x over previous
#include <cuda_runtime.h>
#include <math_constants.h>

// ---------------- problem constants ----------------
constexpr int   kD     = 2048;
constexpr int   kF     = 2048;
constexpr int   kE     = 8;
constexpr int   kT     = 4096;       // tokens = 4*1024
constexpr int   kSlots = 2 * kT;     // top-2 assignments
constexpr int   kBM    = 64;
constexpr float kAlpha = 1.702f;
constexpr float kLimit = 7.0f;
constexpr float kAux   = 0.01f;

// ---------------- device scratch (no allocations allowed) ----------------
__device__ int   g_counts[kE];
__device__ int   g_sid[kE * kT];                 // slot id = token*2 + k
__device__ float g_sw [kE * kT];                 // routing weight for slot
__device__ float g_probs[kT * kE];               // full softmax probs
__device__ float g_act[(size_t)kSlots * kF];     // 64 MB: activated hidden
__device__ float g_partial[(size_t)kSlots * kD]; // 64 MB: weighted expert out

// ---------------- kernel 0: reset counters (graph replays!) --------------
__global__ void moe_init_kernel() {
    if (threadIdx.x < kE) g_counts[threadIdx.x] = 0;
}

// ---------------- kernel 1: router (one warp per token) ------------------
__global__ void moe_router_kernel(const float* __restrict__ x,
                                  const float* __restrict__ rw,
                                  const float* __restrict__ rb) {
    int gw   = (blockIdx.x * blockDim.x + threadIdx.x) >> 5;
    int lane = threadIdx.x & 31;
    if (gw >= kT) return;

    const float* xr = x + (size_t)gw * kD;
    float acc[kE];
#pragma unroll
    for (int e = 0; e < kE; ++e) acc[e] = 0.f;

    for (int d = lane; d < kD; d += 32) {
        float xv = xr[d];
        const float* w = rw + (size_t)d * kE;
#pragma unroll
        for (int e = 0; e < kE; ++e) acc[e] = fmaf(xv, w[e], acc[e]);
    }
#pragma unroll
    for (int e = 0; e < kE; ++e) {
#pragma unroll
        for (int off = 16; off > 0; off >>= 1)
            acc[e] += __shfl_xor_sync(0xffffffffu, acc[e], off);
    }

    if (lane == 0) {
        float lg[kE];
#pragma unroll
        for (int e = 0; e < kE; ++e) lg[e] = acc[e] + rb[e];

        // top-2 (ties -> lowest index, matching lax.top_k)
        int i0 = 0; float l0 = lg[0];
#pragma unroll
        for (int e = 1; e < kE; ++e) if (lg[e] > l0) { l0 = lg[e]; i0 = e; }
        int i1 = -1; float l1 = -CUDART_INF_F;
#pragma unroll
        for (int e = 0; e < kE; ++e)
            if (e != i0 && lg[e] > l1) { l1 = lg[e]; i1 = e; }

        // full softmax probs (needed for aux loss)
        float p[kE]; float s = 0.f;
#pragma unroll
        for (int e = 0; e < kE; ++e) { p[e] = __expf(lg[e] - l0); s += p[e]; }
        float inv = 1.f / s;
#pragma unroll
        for (int e = 0; e < kE; ++e) g_probs[gw * kE + e] = p[e] * inv;

        // routing weights = softmax([l0, l1])
        float r  = __expf(l1 - l0);
        float w0 = 1.f / (1.f + r);
        float w1 = r * w0;

        int s0 = atomicAdd(&g_counts[i0], 1);
        g_sid[i0 * kT + s0] = gw * 2;     g_sw[i0 * kT + s0] = w0;
        int s1 = atomicAdd(&g_counts[i1], 1);
        g_sid[i1 * kT + s1] = gw * 2 + 1; g_sw[i1 * kT + s1] = w1;
    }
}

// ---------------- kernel 2: gathered gate_up GEMM + GLU activation -------
// Tile: 64 rows (assignments) x 64 act-cols (128 weight cols) x K-step 32.
// 256 threads, each owns 4 rows x 4 act-cols (gate+up accumulators).
__global__ void __launch_bounds__(256)
moe_gate_up_kernel(const float* __restrict__ x,
                   const float* __restrict__ wgu,   // [E][D][2F]
                   const float* __restrict__ bgu) { // [E][2F]
    const int e   = blockIdx.y >> 6;
    const int m0  = (blockIdx.y & 63) * kBM;
    const int cnt = g_counts[e];
    if (m0 >= cnt) return;
    const int f0 = blockIdx.x * 64;

    __shared__ __align__(16) float As[32][68];
    __shared__ __align__(16) float Bs[32][128];
    __shared__ int s_sid[kBM];

    const int tid = threadIdx.x;
    if (tid < kBM) {
        int m = m0 + tid;
        s_sid[tid] = (m < cnt) ? g_sid[e * kT + m] : -1;
    }
    __syncthreads();

    // A loader: row = tid&63, k-chunk = (tid>>6)*4 (and +16)
    const int ra = tid & 63;
    const int ka = (tid >> 6) * 4;
    int sidA = s_sid[ra];
    const float* apA = x + (size_t)(sidA < 0 ? 0 : (sidA >> 1)) * kD + ka;

    // B loader: row = (tid>>5) + 8*i, col = (tid&31)*4
    const int rb0 = tid >> 5;
    const int cb  = (tid & 31) * 4;
    const float* bp = wgu + (size_t)e * kD * (2 * kF)
                          + (size_t)rb0 * (2 * kF) + (size_t)f0 * 2 + cb;

    const int ty = tid >> 4;
    const int tx = tid & 15;

    float accg[4][4], accu[4][4];
#pragma unroll
    for (int i = 0; i < 4; ++i)
#pragma unroll
        for (int j = 0; j < 4; ++j) { accg[i][j] = 0.f; accu[i][j] = 0.f; }

    for (int k0 = 0; k0 < kD; k0 += 32) {
        float4 a0 = *(const float4*)(apA + k0);
        float4 a1 = *(const float4*)(apA + k0 + 16);
        float4 b0 = *(const float4*)(bp + (size_t)(k0 +  0) * (2 * kF));
        float4 b1 = *(const float4*)(bp + (size_t)(k0 +  8) * (2 * kF));
        float4 b2 = *(const float4*)(bp + (size_t)(k0 + 16) * (2 * kF));
        float4 b3 = *(const float4*)(bp + (size_t)(k0 + 24) * (2 * kF));
        __syncthreads();
        As[ka + 0][ra] = a0.x; As[ka + 1][ra] = a0.y;
        As[ka + 2][ra] = a0.z; As[ka + 3][ra] = a0.w;
        As[ka + 16][ra] = a1.x; As[ka + 17][ra] = a1.y;
        As[ka + 18][ra] = a1.z; As[ka + 19][ra] = a1.w;
        *(float4*)&Bs[rb0     ][cb] = b0;
        *(float4*)&Bs[rb0 +  8][cb] = b1;
        *(float4*)&Bs[rb0 + 16][cb] = b2;
        *(float4*)&Bs[rb0 + 24][cb] = b3;
        __syncthreads();

#pragma unroll
        for (int kk = 0; kk < 32; ++kk) {
            float4 av  = *(const float4*)&As[kk][ty * 4];
            float4 bv0 = *(const float4*)&Bs[kk][tx * 8];
            float4 bv1 = *(const float4*)&Bs[kk][tx * 8 + 4];
            float a[4]   = {av.x, av.y, av.z, av.w};
            float bgv[4] = {bv0.x, bv0.z, bv1.x, bv1.z};
            float buv[4] = {bv0.y, bv0.w, bv1.y, bv1.w};
#pragma unroll
            for (int i = 0; i < 4; ++i)
#pragma unroll
                for (int j = 0; j < 4; ++j) {
                    accg[i][j] = fmaf(a[i], bgv[j], accg[i][j]);
                    accu[i][j] = fmaf(a[i], buv[j], accu[i][j]);
                }
        }
    }

    // epilogue: bias + clamp + SiLU-GLU, store to act[slot]
#pragma unroll
    for (int i = 0; i < 4; ++i) {
        int r = ty * 4 + i;
        int sid = s_sid[r];
        if (sid < 0) continue;
        float4 o;
        float* ov = (float*)&o;
#pragma unroll
        for (int j = 0; j < 4; ++j) {
            int f = f0 + tx * 4 + j;
            float g = accg[i][j] + bgu[e * (2 * kF) + 2 * f];
            float u = accu[i][j] + bgu[e * (2 * kF) + 2 * f + 1];
            g = fminf(g, kLimit);
            u = fminf(fmaxf(u, -kLimit), kLimit);
            float sig = 1.f / (1.f + __expf(-kAlpha * g));
            ov[j] = (u + 1.f) * (g * sig);
        }
        *(float4*)(g_act + (size_t)sid * kF + f0 + tx * 4) = o;
    }
}

// ---------------- kernel 3: gathered down GEMM (+bias, x routing weight) -
// Tile: 64 rows x 128 out-cols x K-step 32; each thread 4 rows x 8 cols.
__global__ void __launch_bounds__(256)
moe_down_kernel(const float* __restrict__ wdn,   // [E][F][D]
                const float* __restrict__ bdn) { // [E][D]
    const int e   = blockIdx.y >> 6;
    const int m0  = (blockIdx.y & 63) * kBM;
    const int cnt = g_counts[e];
    if (m0 >= cnt) return;
    const int n0 = blockIdx.x * 128;

    __shared__ __align__(16) float As[32][68];
    __shared__ __align__(16) float Bs[32][128];
    __shared__ int   s_sid[kBM];
    __shared__ float s_w[kBM];

    const int tid = threadIdx.x;
    if (tid < kBM) {
        int m = m0 + tid;
        bool v = (m < cnt);
        s_sid[tid] = v ? g_sid[e * kT + m] : -1;
        s_w[tid]   = v ? g_sw [e * kT + m] : 0.f;
    }
    __syncthreads();

    const int ra = tid & 63;
    const int ka = (tid >> 6) * 4;
    int sidA = s_sid[ra];
    const float* apA = g_act + (size_t)(sidA < 0 ? 0 : sidA) * kF + ka;

    const int rb0 = tid >> 5;
    const int cb  = (tid & 31) * 4;
    const float* bp = wdn + (size_t)e * kF * kD + (size_t)rb0 * kD + n0 + cb;

    const int ty = tid >> 4;
    const int tx = tid & 15;

    float acc[4][8];
#pragma unroll
    for (int i = 0; i < 4; ++i)
#pragma unroll
        for (int j = 0; j < 8; ++j) acc[i][j] = 0.f;

    for (int k0 = 0; k0 < kF; k0 += 32) {
        float4 a0 = *(const float4*)(apA + k0);
        float4 a1 = *(const float4*)(apA + k0 + 16);
        float4 b0 = *(const float4*)(bp + (size_t)(k0 +  0) * kD);
        float4 b1 = *(const float4*)(bp + (size_t)(k0 +  8) * kD);
        float4 b2 = *(const float4*)(bp + (size_t)(k0 + 16) * kD);
        float4 b3 = *(const float4*)(bp + (size_t)(k0 + 24) * kD);
        __syncthreads();
        As[ka + 0][ra] = a0.x; As[ka + 1][ra] = a0.y;
        As[ka + 2][ra] = a0.z; As[ka + 3][ra] = a0.w;
        As[ka + 16][ra] = a1.x; As[ka + 17][ra] = a1.y;
        As[ka + 18][ra] = a1.z; As[ka + 19][ra] = a1.w;
        *(float4*)&Bs[rb0     ][cb] = b0;
        *(float4*)&Bs[rb0 +  8][cb] = b1;
        *(float4*)&Bs[rb0 + 16][cb] = b2;
        *(float4*)&Bs[rb0 + 24][cb] = b3;
        __syncthreads();

#pragma unroll
        for (int kk = 0; kk < 32; ++kk) {
            float4 av  = *(const float4*)&As[kk][ty * 4];
            float4 bv0 = *(const float4*)&Bs[kk][tx * 8];
            float4 bv1 = *(const float4*)&Bs[kk][tx * 8 + 4];
            float a[4] = {av.x, av.y, av.z, av.w};
            float b[8] = {bv0.x, bv0.y, bv0.z, bv0.w,
                          bv1.x, bv1.y, bv1.z, bv1.w};
#pragma unroll
            for (int i = 0; i < 4; ++i)
#pragma unroll
                for (int j = 0; j < 8; ++j)
                    acc[i][j] = fmaf(a[i], b[j], acc[i][j]);
        }
    }

#pragma unroll
    for (int i = 0; i < 4; ++i) {
        int r = ty * 4 + i;
        int sid = s_sid[r];
        if (sid < 0) continue;
        float w = s_w[r];
        float4 o0, o1;
        float* ov0 = (float*)&o0;
        float* ov1 = (float*)&o1;
#pragma unroll
        for (int j = 0; j < 4; ++j) {
            int c = n0 + tx * 8 + j;
            ov0[j] = w * (acc[i][j] + bdn[e * kD + c]);
        }
#pragma unroll
        for (int j = 4; j < 8; ++j) {
            int c = n0 + tx * 8 + j;
            ov1[j - 4] = w * (acc[i][j] + bdn[e * kD + c]);
        }
        float* dst = g_partial + (size_t)sid * kD + n0 + tx * 8;
        *(float4*)dst       = o0;
        *(float4*)(dst + 4) = o1;
    }
}

// ---------------- kernel 4: combine the two expert partials per token ----
__global__ void moe_combine_kernel(float* __restrict__ out) {
    size_t idx = (size_t)blockIdx.x * blockDim.x + threadIdx.x; // float4 idx
    // total float4 = kT * kD / 4 = 2,097,152 (grid sized exactly)
    size_t t = idx >> 9;          // / (kD/4)
    size_t c = idx & 511;         // % (kD/4)
    const float4* p = (const float4*)g_partial;
    float4 a = p[(2 * t) * 512 + c];
    float4 b = p[(2 * t + 1) * 512 + c];
    float4 o = make_float4(a.x + b.x, a.y + b.y, a.z + b.z, a.w + b.w);
    ((float4*)out)[idx] = o;
}

// ---------------- kernel 5: expert loads + aux loss (deterministic) ------
__global__ void moe_loss_kernel(float* __restrict__ out_tail) {
    __shared__ float red[256];
    __shared__ float means[kE];
    float s[kE];
#pragma unroll
    for (int e = 0; e < kE; ++e) s[e] = 0.f;
    for (int t = threadIdx.x; t < kT; t += 256) {
        const float* p = g_probs + (size_t)t * kE;
#pragma unroll
        for (int e = 0; e < kE; ++e) s[e] += p[e];
    }
    for (int e = 0; e < kE; ++e) {
        red[threadIdx.x] = s[e];
        __syncthreads();
        for (int off = 128; off > 0; off >>= 1) {
            if (threadIdx.x < off) red[threadIdx.x] += red[threadIdx.x + off];
            __syncthreads();
        }
        if (threadIdx.x == 0) means[e] = red[0] / (float)kT;
        __syncthreads();
    }
    if (threadIdx.x == 0) {
        float loss = 0.f;
        for (int e = 0; e < kE; ++e) {
            float frac = (float)g_counts[e] / (float)(kT * 2);
            out_tail[e] = frac;                 // expert_loads
            loss += frac * means[e];
        }
        out_tail[kE] = kAux * (float)kE * loss; // load_balancing_loss
    }
}

// ---------------- launch ----------------
extern "C" void kernel_launch(void* const* d_in, const int* in_sizes, int n_in,
                              void* d_out, int out_size) {
    const float* x   = (const float*)d_in[0];
    const float* rw  = (const float*)d_in[1];
    const float* rb  = (const float*)d_in[2];
    const float* wgu = (const float*)d_in[3];
    const float* bgu = (const float*)d_in[4];
    const float* wdn = (const float*)d_in[5];
    const float* bdn = (const float*)d_in[6];
    float* out = (float*)d_out;

    moe_init_kernel<<<1, 32>>>();
    moe_router_kernel<<<(kT * 32) / 256, 256>>>(x, rw, rb);

    // worst case: one expert owns all 4096 tokens -> 64 M-tiles per expert
    dim3 g1(kF / 64, kE * 64);   // (32, 512)
    moe_gate_up_kernel<<<g1, 256>>>(x, wgu, bgu);

    dim3 g2(kD / 128, kE * 64);  // (16, 512)
    moe_down_kernel<<<g2, 256>>>(wdn, bdn);

    moe_combine_kernel<<<(kT * kD / 4) / 256, 256>>>(out);
    moe_loss_kernel<<<1, 256>>>(out + (size_t)kT * kD);
}

// round 14
// speedup vs baseline: 2.8415x; 2.8413x over previous
#include <cuda_runtime.h>
#include <cuda_bf16.h>
#include <math_constants.h>
#include <cstdint>

// ---------------- problem constants ----------------
constexpr int   kD     = 2048;
constexpr int   kF     = 2048;
constexpr int   kE     = 8;
constexpr int   kT     = 4096;
constexpr int   kSlots = 2 * kT;
constexpr float kAlpha = 1.702f;
constexpr float kLimit = 7.0f;
constexpr float kAux   = 0.01f;

// smem layout for the HMMA kernels
constexpr int PITCH    = 80;            // 32 bf16 (64B) + 16B pad -> conflict-free ldmatrix
constexpr int TSZ      = 128 * PITCH;   // 10240 bytes per matrix tile
constexpr int SMS_SID  = 0;             // 128 ints
constexpr int SMS_W    = 512;           // 128 floats (down only)
constexpr int SMS_BIAS = 1024;          // 128 floats
constexpr int SMS_TILE = 1536;          // 8 tiles: [stage][Ah,Al,Bh,Bl]
constexpr int SM_TOTAL = SMS_TILE + 8 * TSZ;   // 83456

// ---------------- device scratch (no allocations allowed) ----------------
__device__ int   g_counts[kE];
__device__ int   g_sid[kE * kT];
__device__ float g_sw [kE * kT];
__device__ float g_probs[kT * kE];
__device__ __align__(16) float g_partial[(size_t)kSlots * kD];
__device__ __align__(16) __nv_bfloat16 g_xh[(size_t)kT * kD];
__device__ __align__(16) __nv_bfloat16 g_xl[(size_t)kT * kD];
__device__ __align__(16) __nv_bfloat16 g_guT_h[(size_t)kE * 2 * kF * kD];
__device__ __align__(16) __nv_bfloat16 g_guT_l[(size_t)kE * 2 * kF * kD];
__device__ __align__(16) __nv_bfloat16 g_dnT_h[(size_t)kE * kD * kF];
__device__ __align__(16) __nv_bfloat16 g_dnT_l[(size_t)kE * kD * kF];
__device__ __align__(16) __nv_bfloat16 g_act_h[(size_t)kSlots * kF];
__device__ __align__(16) __nv_bfloat16 g_act_l[(size_t)kSlots * kF];

// ---------------- PTX helpers (all base-sm_103 legal) ----------------
__device__ __forceinline__ uint32_t s2u(const void* p) {
    uint32_t a;
    asm("{ .reg .u64 t; cvta.to.shared.u64 t, %1; cvt.u32.u64 %0, t; }"
        : "=r"(a) : "l"(p));
    return a;
}
__device__ __forceinline__ void cpa(uint32_t d, const void* s) {
    asm volatile("cp.async.cg.shared.global [%0], [%1], 16;"
                 :: "r"(d), "l"(s) : "memory");
}
__device__ __forceinline__ void cp_commit() {
    asm volatile("cp.async.commit_group;" ::: "memory");
}
template <int N>
__device__ __forceinline__ void cp_wait() {
    asm volatile("cp.async.wait_group %0;" :: "n"(N) : "memory");
}
__device__ __forceinline__ void ldsm4(uint32_t a, uint32_t& r0, uint32_t& r1,
                                      uint32_t& r2, uint32_t& r3) {
    asm volatile("ldmatrix.sync.aligned.m8n8.x4.shared.b16 {%0,%1,%2,%3}, [%4];"
                 : "=r"(r0), "=r"(r1), "=r"(r2), "=r"(r3) : "r"(a));
}
__device__ __forceinline__ void mma_bf16(float* d, const uint32_t* a,
                                         uint32_t b0, uint32_t b1) {
    asm volatile(
        "mma.sync.aligned.m16n8k16.row.col.f32.bf16.bf16.f32 "
        "{%0,%1,%2,%3}, {%4,%5,%6,%7}, {%8,%9}, {%0,%1,%2,%3};"
        : "+f"(d[0]), "+f"(d[1]), "+f"(d[2]), "+f"(d[3])
        : "r"(a[0]), "r"(a[1]), "r"(a[2]), "r"(a[3]), "r"(b0), "r"(b1));
}

// ---------------- shared GEMM core: 128x128, K=2048, bf16x3 --------------
// pX*0 pointers: row (tid>>2), pX*1: row (tid>>2)+64, both offset by (tid&3)*16B.
__device__ __forceinline__ void run_gemm(
    char* smem, uint32_t sb, int tid,
    const char* pAh0, const char* pAh1, const char* pAl0, const char* pAl1,
    const char* pBh0, const char* pBh1, const char* pBl0, const char* pBl1,
    float (*acc)[4][4])
{
    const int wid = tid >> 5, lane = tid & 31;
    const int wm = (wid >> 2) * 64, wn = (wid & 3) * 32;
    const int r0 = tid >> 2, r1v = r0 + 64, ccol = tid & 3;
    const uint32_t d0 = sb + SMS_TILE + (uint32_t)r0  * PITCH + ccol * 16;
    const uint32_t d1 = sb + SMS_TILE + (uint32_t)r1v * PITCH + ccol * 16;

    // prologue: chunk 0 -> stage 0
    cpa(d0 + 0 * TSZ, pAh0); cpa(d1 + 0 * TSZ, pAh1);
    cpa(d0 + 1 * TSZ, pAl0); cpa(d1 + 1 * TSZ, pAl1);
    cpa(d0 + 2 * TSZ, pBh0); cpa(d1 + 2 * TSZ, pBh1);
    cpa(d0 + 3 * TSZ, pBl0); cpa(d1 + 3 * TSZ, pBl1);
    cp_commit();

    const uint32_t lrow = lane & 15, lsel = (uint32_t)lane >> 4;
    for (int c = 0; c < 64; ++c) {
        cp_wait<0>();          // chunk c resident
        __syncthreads();
        if (c + 1 < 64) {      // prefetch chunk c+1 into the other stage
            uint32_t st = (uint32_t)((c + 1) & 1) * 4 * TSZ;
            size_t off = (size_t)(c + 1) * 64;   // 32 bf16 per chunk
            cpa(d0 + st + 0 * TSZ, pAh0 + off); cpa(d1 + st + 0 * TSZ, pAh1 + off);
            cpa(d0 + st + 1 * TSZ, pAl0 + off); cpa(d1 + st + 1 * TSZ, pAl1 + off);
            cpa(d0 + st + 2 * TSZ, pBh0 + off); cpa(d1 + st + 2 * TSZ, pBh1 + off);
            cpa(d0 + st + 3 * TSZ, pBl0 + off); cpa(d1 + st + 3 * TSZ, pBl1 + off);
            cp_commit();
        }
        const uint32_t base = sb + SMS_TILE + (uint32_t)(c & 1) * 4 * TSZ;
#pragma unroll
        for (int k16 = 0; k16 < 2; ++k16) {
            const uint32_t koff = (uint32_t)k16 * 32 + lsel * 16;
            uint32_t ah[4][4], al[4][4], bh[2][4], bl[2][4];
#pragma unroll
            for (int mi = 0; mi < 4; ++mi) {
                uint32_t a = base + (wm + mi * 16 + lrow) * PITCH + koff;
                ldsm4(a,        ah[mi][0], ah[mi][1], ah[mi][2], ah[mi][3]);
                ldsm4(a + TSZ,  al[mi][0], al[mi][1], al[mi][2], al[mi][3]);
            }
#pragma unroll
            for (int np = 0; np < 2; ++np) {
                uint32_t a = base + 2 * TSZ + (wn + np * 16 + lrow) * PITCH + koff;
                ldsm4(a,        bh[np][0], bh[np][1], bh[np][2], bh[np][3]);
                ldsm4(a + TSZ,  bl[np][0], bl[np][1], bl[np][2], bl[np][3]);
            }
#pragma unroll
            for (int mi = 0; mi < 4; ++mi)
#pragma unroll
                for (int ni = 0; ni < 4; ++ni) {
                    const int np = ni >> 1, s = ni & 1;
                    mma_bf16(acc[mi][ni], ah[mi], bh[np][s], bh[np][s + 2]);
                    mma_bf16(acc[mi][ni], ah[mi], bl[np][s], bl[np][s + 2]);
                    mma_bf16(acc[mi][ni], al[mi], bh[np][s], bh[np][s + 2]);
                }
        }
        __syncthreads();       // stage c fully consumed before overwrite at c+2
    }
}

// ---------------- kernel 0: reset counters ----------------
__global__ void moe_init_kernel() {
    if (threadIdx.x < kE) g_counts[threadIdx.x] = 0;
}

// ---------------- kernel 1: router (one warp per token) ----------------
__global__ void moe_router_kernel(const float* __restrict__ x,
                                  const float* __restrict__ rw,
                                  const float* __restrict__ rb) {
    int gw   = (blockIdx.x * blockDim.x + threadIdx.x) >> 5;
    int lane = threadIdx.x & 31;
    if (gw >= kT) return;

    const float* xr = x + (size_t)gw * kD;
    float acc[kE];
#pragma unroll
    for (int e = 0; e < kE; ++e) acc[e] = 0.f;
    for (int d = lane; d < kD; d += 32) {
        float xv = xr[d];
        const float* w = rw + (size_t)d * kE;
#pragma unroll
        for (int e = 0; e < kE; ++e) acc[e] = fmaf(xv, w[e], acc[e]);
    }
#pragma unroll
    for (int e = 0; e < kE; ++e)
#pragma unroll
        for (int off = 16; off > 0; off >>= 1)
            acc[e] += __shfl_xor_sync(0xffffffffu, acc[e], off);

    if (lane == 0) {
        float lg[kE];
#pragma unroll
        for (int e = 0; e < kE; ++e) lg[e] = acc[e] + rb[e];

        int i0 = 0; float l0 = lg[0];
#pragma unroll
        for (int e = 1; e < kE; ++e) if (lg[e] > l0) { l0 = lg[e]; i0 = e; }
        int i1 = -1; float l1 = -CUDART_INF_F;
#pragma unroll
        for (int e = 0; e < kE; ++e)
            if (e != i0 && lg[e] > l1) { l1 = lg[e]; i1 = e; }

        float p[kE]; float s = 0.f;
#pragma unroll
        for (int e = 0; e < kE; ++e) { p[e] = __expf(lg[e] - l0); s += p[e]; }
        float inv = 1.f / s;
#pragma unroll
        for (int e = 0; e < kE; ++e) g_probs[gw * kE + e] = p[e] * inv;

        float r  = __expf(l1 - l0);
        float w0 = 1.f / (1.f + r);
        float w1 = r * w0;

        int s0 = atomicAdd(&g_counts[i0], 1);
        g_sid[i0 * kT + s0] = gw * 2;     g_sw[i0 * kT + s0] = w0;
        int s1 = atomicAdd(&g_counts[i1], 1);
        g_sid[i1 * kT + s1] = gw * 2 + 1; g_sw[i1 * kT + s1] = w1;
    }
}

// ---------------- kernel 2a: x -> bf16 hi/lo ----------------
__global__ void conv_x_kernel(const float* __restrict__ x) {
    size_t i = (size_t)blockIdx.x * blockDim.x + threadIdx.x;  // float4 index
    float4 v = ((const float4*)x)[i];
    float f[4] = {v.x, v.y, v.z, v.w};
    uint16_t h[4], l[4];
#pragma unroll
    for (int j = 0; j < 4; ++j) {
        __nv_bfloat16 hb = __float2bfloat16(f[j]);
        h[j] = __bfloat16_as_ushort(hb);
        l[j] = __bfloat16_as_ushort(__float2bfloat16(f[j] - __bfloat162float(hb)));
    }
    ((uint2*)g_xh)[i] = make_uint2(((uint32_t)h[1] << 16) | h[0],
                                   ((uint32_t)h[3] << 16) | h[2]);
    ((uint2*)g_xl)[i] = make_uint2(((uint32_t)l[1] << 16) | l[0],
                                   ((uint32_t)l[3] << 16) | l[2]);
}

// ---------------- kernel 2b: wgu [E][D][2F] -> [E][2F][D] bf16 hi/lo ------
__global__ void conv_guT_kernel(const float* __restrict__ w) {
    __shared__ float tile[32][33];
    const int e = blockIdx.z, n0 = blockIdx.x * 32, d0 = blockIdx.y * 32;
    const int t = threadIdx.x, col = t & 31, r4 = t >> 5;
    const float* src = w + ((size_t)e * kD + d0) * (2 * kF) + n0;
#pragma unroll
    for (int i = 0; i < 4; ++i) {
        int r = r4 + i * 8;
        tile[r][col] = src[(size_t)r * (2 * kF) + col];
    }
    __syncthreads();
#pragma unroll
    for (int i = 0; i < 4; ++i) {
        int r = r4 + i * 8;
        float v = tile[col][r];
        size_t o = ((size_t)e * (2 * kF) + n0 + r) * kD + d0 + col;
        __nv_bfloat16 hb = __float2bfloat16(v);
        g_guT_h[o] = hb;
        g_guT_l[o] = __float2bfloat16(v - __bfloat162float(hb));
    }
}

// ---------------- kernel 2c: wdn [E][F][D] -> [E][D][F] bf16 hi/lo --------
__global__ void conv_dnT_kernel(const float* __restrict__ w) {
    __shared__ float tile[32][33];
    const int e = blockIdx.z, d0 = blockIdx.x * 32, f0 = blockIdx.y * 32;
    const int t = threadIdx.x, col = t & 31, r4 = t >> 5;
    const float* src = w + ((size_t)e * kF + f0) * kD + d0;
#pragma unroll
    for (int i = 0; i < 4; ++i) {
        int r = r4 + i * 8;
        tile[r][col] = src[(size_t)r * kD + col];
    }
    __syncthreads();
#pragma unroll
    for (int i = 0; i < 4; ++i) {
        int r = r4 + i * 8;
        float v = tile[col][r];
        size_t o = ((size_t)e * kD + d0 + r) * kF + f0 + col;
        __nv_bfloat16 hb = __float2bfloat16(v);
        g_dnT_h[o] = hb;
        g_dnT_l[o] = __float2bfloat16(v - __bfloat162float(hb));
    }
}

// ---------------- kernel 3: gate_up GEMM (HMMA, bf16x3) -------------------
__global__ void __launch_bounds__(256, 1)
moe_gu_hmma(const float* __restrict__ bgu) {
    extern __shared__ char smem[];
    const int e   = blockIdx.y >> 5;
    const int m0  = (blockIdx.y & 31) * 128;
    const int cnt = g_counts[e];
    if (m0 >= cnt) return;
    const int n0 = blockIdx.x * 128;

    const uint32_t sb = s2u(smem);
    int*   s_sid  = (int*)(smem + SMS_SID);
    float* s_bias = (float*)(smem + SMS_BIAS);
    const int tid = threadIdx.x;
    if (tid < 128) {
        int m = m0 + tid;
        s_sid[tid]  = (m < cnt) ? g_sid[e * kT + m] : -1;
        s_bias[tid] = bgu[e * (2 * kF) + n0 + tid];
    }
    __syncthreads();

    const int r0 = tid >> 2, r1v = r0 + 64, ccol = tid & 3;
    int sid0 = s_sid[r0], sid1 = s_sid[r1v];
    size_t t0 = (size_t)(sid0 < 0 ? 0 : (sid0 >> 1)) * kD;
    size_t t1 = (size_t)(sid1 < 0 ? 0 : (sid1 >> 1)) * kD;
    size_t b0o = ((size_t)e * (2 * kF) + n0 + r0)  * kD;
    size_t b1o = ((size_t)e * (2 * kF) + n0 + r1v) * kD;

    float acc[4][4][4];
#pragma unroll
    for (int i = 0; i < 4; ++i)
#pragma unroll
        for (int j = 0; j < 4; ++j)
#pragma unroll
            for (int q = 0; q < 4; ++q) acc[i][j][q] = 0.f;

    run_gemm(smem, sb, tid,
             (const char*)(g_xh + t0) + ccol * 16,
             (const char*)(g_xh + t1) + ccol * 16,
             (const char*)(g_xl + t0) + ccol * 16,
             (const char*)(g_xl + t1) + ccol * 16,
             (const char*)(g_guT_h + b0o) + ccol * 16,
             (const char*)(g_guT_h + b1o) + ccol * 16,
             (const char*)(g_guT_l + b0o) + ccol * 16,
             (const char*)(g_guT_l + b1o) + ccol * 16,
             acc);

    // epilogue: bias + clamp + SiLU-GLU -> stage act hi/lo in smem
    const int wid = tid >> 5, lane = tid & 31;
    const int wm = (wid >> 2) * 64, wn = (wid & 3) * 32;
#pragma unroll
    for (int mi = 0; mi < 4; ++mi) {
        int rA = wm + mi * 16 + (lane >> 2);
        int rB = rA + 8;
#pragma unroll
        for (int ni = 0; ni < 4; ++ni) {
            int ncol = wn + ni * 8 + (lane & 3) * 2;
            float bg = s_bias[ncol], bu = s_bias[ncol + 1];
            int fl = ncol >> 1;
            float g0 = fminf(acc[mi][ni][0] + bg, kLimit);
            float u0 = fminf(fmaxf(acc[mi][ni][1] + bu, -kLimit), kLimit);
            float a0 = (u0 + 1.f) * (g0 / (1.f + __expf(-kAlpha * g0)));
            float g1 = fminf(acc[mi][ni][2] + bg, kLimit);
            float u1 = fminf(fmaxf(acc[mi][ni][3] + bu, -kLimit), kLimit);
            float a1 = (u1 + 1.f) * (g1 / (1.f + __expf(-kAlpha * g1)));
            __nv_bfloat16 h0 = __float2bfloat16(a0);
            __nv_bfloat16 l0 = __float2bfloat16(a0 - __bfloat162float(h0));
            __nv_bfloat16 h1 = __float2bfloat16(a1);
            __nv_bfloat16 l1 = __float2bfloat16(a1 - __bfloat162float(h1));
            *(__nv_bfloat16*)(smem + SMS_TILE +         rA * 128 + fl * 2) = h0;
            *(__nv_bfloat16*)(smem + SMS_TILE + 16384 + rA * 128 + fl * 2) = l0;
            *(__nv_bfloat16*)(smem + SMS_TILE +         rB * 128 + fl * 2) = h1;
            *(__nv_bfloat16*)(smem + SMS_TILE + 16384 + rB * 128 + fl * 2) = l1;
        }
    }
    __syncthreads();

    const int f0 = blockIdx.x * 64;
#pragma unroll
    for (int i = 0; i < 4; ++i) {
        int chunk = tid + i * 256;           // 1024 x 16B chunks
        int row = chunk >> 3, c8 = chunk & 7;
        int sid = s_sid[row];
        if (sid >= 0) {
            uint4 vh = *(uint4*)(smem + SMS_TILE +         row * 128 + c8 * 16);
            uint4 vl = *(uint4*)(smem + SMS_TILE + 16384 + row * 128 + c8 * 16);
            *(uint4*)(g_act_h + (size_t)sid * kF + f0 + c8 * 8) = vh;
            *(uint4*)(g_act_l + (size_t)sid * kF + f0 + c8 * 8) = vl;
        }
    }
}

// ---------------- kernel 4: down GEMM (HMMA, bf16x3) ----------------------
__global__ void __launch_bounds__(256, 1)
moe_dn_hmma(const float* __restrict__ bdn) {
    extern __shared__ char smem[];
    const int e   = blockIdx.y >> 5;
    const int m0  = (blockIdx.y & 31) * 128;
    const int cnt = g_counts[e];
    if (m0 >= cnt) return;
    const int n0 = blockIdx.x * 128;

    const uint32_t sb = s2u(smem);
    int*   s_sid  = (int*)(smem + SMS_SID);
    float* s_w    = (float*)(smem + SMS_W);
    float* s_bias = (float*)(smem + SMS_BIAS);
    const int tid = threadIdx.x;
    if (tid < 128) {
        int m = m0 + tid;
        bool v = (m < cnt);
        s_sid[tid]  = v ? g_sid[e * kT + m] : -1;
        s_w[tid]    = v ? g_sw[e * kT + m] : 0.f;
        s_bias[tid] = bdn[e * kD + n0 + tid];
    }
    __syncthreads();

    const int r0 = tid >> 2, r1v = r0 + 64, ccol = tid & 3;
    int sid0 = s_sid[r0], sid1 = s_sid[r1v];
    size_t t0 = (size_t)(sid0 < 0 ? 0 : sid0) * kF;
    size_t t1 = (size_t)(sid1 < 0 ? 0 : sid1) * kF;
    size_t b0o = ((size_t)e * kD + n0 + r0)  * kF;
    size_t b1o = ((size_t)e * kD + n0 + r1v) * kF;

    float acc[4][4][4];
#pragma unroll
    for (int i = 0; i < 4; ++i)
#pragma unroll
        for (int j = 0; j < 4; ++j)
#pragma unroll
            for (int q = 0; q < 4; ++q) acc[i][j][q] = 0.f;

    run_gemm(smem, sb, tid,
             (const char*)(g_act_h + t0) + ccol * 16,
             (const char*)(g_act_h + t1) + ccol * 16,
             (const char*)(g_act_l + t0) + ccol * 16,
             (const char*)(g_act_l + t1) + ccol * 16,
             (const char*)(g_dnT_h + b0o) + ccol * 16,
             (const char*)(g_dnT_h + b1o) + ccol * 16,
             (const char*)(g_dnT_l + b0o) + ccol * 16,
             (const char*)(g_dnT_l + b1o) + ccol * 16,
             acc);

    // epilogue: out = w_slot * (acc + bias) -> per-slot partial rows
    const int wid = tid >> 5, lane = tid & 31;
    const int wm = (wid >> 2) * 64, wn = (wid & 3) * 32;
#pragma unroll
    for (int mi = 0; mi < 4; ++mi) {
        int rA = wm + mi * 16 + (lane >> 2);
        int rB = rA + 8;
        int sidA = s_sid[rA], sidB = s_sid[rB];
        float wA = s_w[rA], wB = s_w[rB];
#pragma unroll
        for (int ni = 0; ni < 4; ++ni) {
            int ncol = wn + ni * 8 + (lane & 3) * 2;
            float b0 = s_bias[ncol], b1 = s_bias[ncol + 1];
            if (sidA >= 0) {
                float2 o = make_float2(wA * (acc[mi][ni][0] + b0),
                                       wA * (acc[mi][ni][1] + b1));
                *(float2*)(g_partial + (size_t)sidA * kD + n0 + ncol) = o;
            }
            if (sidB >= 0) {
                float2 o = make_float2(wB * (acc[mi][ni][2] + b0),
                                       wB * (acc[mi][ni][3] + b1));
                *(float2*)(g_partial + (size_t)sidB * kD + n0 + ncol) = o;
            }
        }
    }
}

// ---------------- kernel 5: combine two expert partials per token ---------
__global__ void moe_combine_kernel(float* __restrict__ out) {
    size_t idx = (size_t)blockIdx.x * blockDim.x + threadIdx.x; // float4 idx
    size_t t = idx >> 9;
    size_t c = idx & 511;
    const float4* p = (const float4*)g_partial;
    float4 a = p[(2 * t) * 512 + c];
    float4 b = p[(2 * t + 1) * 512 + c];
    ((float4*)out)[idx] = make_float4(a.x + b.x, a.y + b.y, a.z + b.z, a.w + b.w);
}

// ---------------- kernel 6: expert loads + aux loss -----------------------
__global__ void moe_loss_kernel(float* __restrict__ out_tail) {
    __shared__ float red[256];
    __shared__ float means[kE];
    float s[kE];
#pragma unroll
    for (int e = 0; e < kE; ++e) s[e] = 0.f;
    for (int t = threadIdx.x; t < kT; t += 256) {
        const float* p = g_probs + (size_t)t * kE;
#pragma unroll
        for (int e = 0; e < kE; ++e) s[e] += p[e];
    }
    for (int e = 0; e < kE; ++e) {
        red[threadIdx.x] = s[e];
        __syncthreads();
        for (int off = 128; off > 0; off >>= 1) {
            if (threadIdx.x < off) red[threadIdx.x] += red[threadIdx.x + off];
            __syncthreads();
        }
        if (threadIdx.x == 0) means[e] = red[0] / (float)kT;
        __syncthreads();
    }
    if (threadIdx.x == 0) {
        float loss = 0.f;
        for (int e = 0; e < kE; ++e) {
            float frac = (float)g_counts[e] / (float)(kT * 2);
            out_tail[e] = frac;
            loss += frac * means[e];
        }
        out_tail[kE] = kAux * (float)kE * loss;
    }
}

// ---------------- launch ----------------
extern "C" void kernel_launch(void* const* d_in, const int* in_sizes, int n_in,
                              void* d_out, int out_size) {
    const float* x   = (const float*)d_in[0];
    const float* rw  = (const float*)d_in[1];
    const float* rb  = (const float*)d_in[2];
    const float* wgu = (const float*)d_in[3];
    const float* bgu = (const float*)d_in[4];
    const float* wdn = (const float*)d_in[5];
    const float* bdn = (const float*)d_in[6];
    float* out = (float*)d_out;

    cudaFuncSetAttribute(moe_gu_hmma,
                         cudaFuncAttributeMaxDynamicSharedMemorySize, SM_TOTAL);
    cudaFuncSetAttribute(moe_dn_hmma,
                         cudaFuncAttributeMaxDynamicSharedMemorySize, SM_TOTAL);

    moe_init_kernel<<<1, 32>>>();
    moe_router_kernel<<<(kT * 32) / 256, 256>>>(x, rw, rb);

    conv_x_kernel<<<(kT * kD / 4) / 256, 256>>>(x);
    conv_guT_kernel<<<dim3(2 * kF / 32, kD / 32, kE), 256>>>(wgu);
    conv_dnT_kernel<<<dim3(kD / 32, kF / 32, kE), 256>>>(wdn);

    // worst case: one expert owns all tokens -> 32 M-tiles of 128 per expert
    moe_gu_hmma<<<dim3(2 * kF / 128, kE * 32), 256, SM_TOTAL>>>(bgu);
    moe_dn_hmma<<<dim3(kD / 128,     kE * 32), 256, SM_TOTAL>>>(bdn);

    moe_combine_kernel<<<(kT * kD / 4) / 256, 256>>>(out);
    moe_loss_kernel<<<1, 256>>>(out + (size_t)kT * kD);
}

// round 15
// speedup vs baseline: 2.8473x; 1.0021x over previous
#include <cuda_runtime.h>
#include <cuda_bf16.h>
#include <math_constants.h>
#include <cstdint>

// ---------------- problem constants ----------------
constexpr int   kD     = 2048;
constexpr int   kF     = 2048;
constexpr int   kE     = 8;
constexpr int   kT     = 4096;
constexpr int   kSlots = 2 * kT;
constexpr float kAlpha = 1.702f;
constexpr float kLimit = 7.0f;
constexpr float kAux   = 0.01f;

// smem layout for the HMMA kernels
constexpr int PITCH    = 80;            // 32 bf16 (64B) + 16B pad -> conflict-free ldmatrix
constexpr int TSZ      = 128 * PITCH;   // 10240 bytes per matrix tile
constexpr int STAGES   = 4;
constexpr int STG      = 4 * TSZ;       // bytes per stage (Ah,Al,Bh,Bl)
constexpr int SMS_SID  = 0;             // 128 ints
constexpr int SMS_W    = 512;           // 128 floats (down only)
constexpr int SMS_BIAS = 1024;          // 128 floats
constexpr int SMS_TILE = 1536;          // STAGES x [Ah,Al,Bh,Bl]
constexpr int SM_TOTAL = SMS_TILE + STAGES * STG;   // 165376

// ---------------- device scratch (no allocations allowed) ----------------
__device__ int   g_counts[kE];
__device__ int   g_sid[kE * kT];
__device__ float g_sw [kE * kT];
__device__ float g_probs[kT * kE];
__device__ __align__(16) float g_partial[(size_t)kSlots * kD];
__device__ __align__(16) __nv_bfloat16 g_xh[(size_t)kT * kD];
__device__ __align__(16) __nv_bfloat16 g_xl[(size_t)kT * kD];
__device__ __align__(16) __nv_bfloat16 g_guT_h[(size_t)kE * 2 * kF * kD];
__device__ __align__(16) __nv_bfloat16 g_guT_l[(size_t)kE * 2 * kF * kD];
__device__ __align__(16) __nv_bfloat16 g_dnT_h[(size_t)kE * kD * kF];
__device__ __align__(16) __nv_bfloat16 g_dnT_l[(size_t)kE * kD * kF];
__device__ __align__(16) __nv_bfloat16 g_act_h[(size_t)kSlots * kF];
__device__ __align__(16) __nv_bfloat16 g_act_l[(size_t)kSlots * kF];

// ---------------- PTX helpers (all base-sm_103 legal) ----------------
__device__ __forceinline__ uint32_t s2u(const void* p) {
    uint32_t a;
    asm("{ .reg .u64 t; cvta.to.shared.u64 t, %1; cvt.u32.u64 %0, t; }"
        : "=r"(a) : "l"(p));
    return a;
}
__device__ __forceinline__ void cpa(uint32_t d, const void* s) {
    asm volatile("cp.async.cg.shared.global [%0], [%1], 16;"
                 :: "r"(d), "l"(s) : "memory");
}
__device__ __forceinline__ void cp_commit() {
    asm volatile("cp.async.commit_group;" ::: "memory");
}
template <int N>
__device__ __forceinline__ void cp_wait() {
    asm volatile("cp.async.wait_group %0;" :: "n"(N) : "memory");
}
__device__ __forceinline__ void ldsm4(uint32_t a, uint32_t& r0, uint32_t& r1,
                                      uint32_t& r2, uint32_t& r3) {
    asm volatile("ldmatrix.sync.aligned.m8n8.x4.shared.b16 {%0,%1,%2,%3}, [%4];"
                 : "=r"(r0), "=r"(r1), "=r"(r2), "=r"(r3) : "r"(a));
}
__device__ __forceinline__ void mma_bf16(float* d, const uint32_t* a,
                                         uint32_t b0, uint32_t b1) {
    asm volatile(
        "mma.sync.aligned.m16n8k16.row.col.f32.bf16.bf16.f32 "
        "{%0,%1,%2,%3}, {%4,%5,%6,%7}, {%8,%9}, {%0,%1,%2,%3};"
        : "+f"(d[0]), "+f"(d[1]), "+f"(d[2]), "+f"(d[3])
        : "r"(a[0]), "r"(a[1]), "r"(a[2]), "r"(a[3]), "r"(b0), "r"(b1));
}

// ---------------- shared GEMM core: 128x128, K=2048, bf16x3 --------------
// 4-stage cp.async pipeline, BK=32, one __syncthreads per chunk.
// pX*0 pointers: row (tid>>2), pX*1: row (tid>>2)+64, both offset by (tid&3)*16B.
__device__ __forceinline__ void run_gemm(
    char* smem, uint32_t sb, int tid,
    const char* pAh0, const char* pAh1, const char* pAl0, const char* pAl1,
    const char* pBh0, const char* pBh1, const char* pBl0, const char* pBl1,
    float (*acc)[4][4])
{
    const int wid = tid >> 5, lane = tid & 31;
    const int wm = (wid >> 2) * 64, wn = (wid & 3) * 32;
    const int r0 = tid >> 2, r1v = r0 + 64, ccol = tid & 3;
    const uint32_t d0 = sb + SMS_TILE + (uint32_t)r0  * PITCH + ccol * 16;
    const uint32_t d1 = sb + SMS_TILE + (uint32_t)r1v * PITCH + ccol * 16;

    // prologue: chunks 0..2 -> stages 0..2, one commit group each
#pragma unroll
    for (int s = 0; s < 3; ++s) {
        const uint32_t st = (uint32_t)s * STG;
        const size_t  off = (size_t)s * 64;      // 32 bf16 = 64 bytes per chunk
        cpa(d0 + st + 0 * TSZ, pAh0 + off); cpa(d1 + st + 0 * TSZ, pAh1 + off);
        cpa(d0 + st + 1 * TSZ, pAl0 + off); cpa(d1 + st + 1 * TSZ, pAl1 + off);
        cpa(d0 + st + 2 * TSZ, pBh0 + off); cpa(d1 + st + 2 * TSZ, pBh1 + off);
        cpa(d0 + st + 3 * TSZ, pBl0 + off); cpa(d1 + st + 3 * TSZ, pBl1 + off);
        cp_commit();
    }

    const uint32_t lrow = lane & 15, lsel = (uint32_t)lane >> 4;
    for (int c = 0; c < 64; ++c) {
        cp_wait<2>();          // group c landed (c+1, c+2 may still be in flight)
        __syncthreads();       // all warps done with stage (c+3)&3 (read at c-1)
        {
            const int cn = c + 3;
            if (cn < 64) {
                const uint32_t st = (uint32_t)(cn & 3) * STG;
                const size_t  off = (size_t)cn * 64;
                cpa(d0 + st + 0 * TSZ, pAh0 + off); cpa(d1 + st + 0 * TSZ, pAh1 + off);
                cpa(d0 + st + 1 * TSZ, pAl0 + off); cpa(d1 + st + 1 * TSZ, pAl1 + off);
                cpa(d0 + st + 2 * TSZ, pBh0 + off); cpa(d1 + st + 2 * TSZ, pBh1 + off);
                cpa(d0 + st + 3 * TSZ, pBl0 + off); cpa(d1 + st + 3 * TSZ, pBl1 + off);
            }
            cp_commit();       // possibly empty group keeps wait-count uniform
        }
        const uint32_t base = sb + SMS_TILE + (uint32_t)(c & 3) * STG;
#pragma unroll
        for (int k16 = 0; k16 < 2; ++k16) {
            const uint32_t koff = (uint32_t)k16 * 32 + lsel * 16;
            uint32_t ah[4][4], al[4][4], bh[2][4], bl[2][4];
#pragma unroll
            for (int mi = 0; mi < 4; ++mi) {
                uint32_t a = base + (wm + mi * 16 + lrow) * PITCH + koff;
                ldsm4(a,        ah[mi][0], ah[mi][1], ah[mi][2], ah[mi][3]);
                ldsm4(a + TSZ,  al[mi][0], al[mi][1], al[mi][2], al[mi][3]);
            }
#pragma unroll
            for (int np = 0; np < 2; ++np) {
                uint32_t a = base + 2 * TSZ + (wn + np * 16 + lrow) * PITCH + koff;
                ldsm4(a,        bh[np][0], bh[np][1], bh[np][2], bh[np][3]);
                ldsm4(a + TSZ,  bl[np][0], bl[np][1], bl[np][2], bl[np][3]);
            }
#pragma unroll
            for (int mi = 0; mi < 4; ++mi)
#pragma unroll
                for (int ni = 0; ni < 4; ++ni) {
                    const int np = ni >> 1, s = ni & 1;
                    mma_bf16(acc[mi][ni], ah[mi], bh[np][s], bh[np][s + 2]);
                    mma_bf16(acc[mi][ni], ah[mi], bl[np][s], bl[np][s + 2]);
                    mma_bf16(acc[mi][ni], al[mi], bh[np][s], bh[np][s + 2]);
                }
        }
    }
}

// ---------------- kernel 0: reset counters ----------------
__global__ void moe_init_kernel() {
    if (threadIdx.x < kE) g_counts[threadIdx.x] = 0;
}

// ---------------- kernel 1: router (one warp per token) ----------------
__global__ void moe_router_kernel(const float* __restrict__ x,
                                  const float* __restrict__ rw,
                                  const float* __restrict__ rb) {
    int gw   = (blockIdx.x * blockDim.x + threadIdx.x) >> 5;
    int lane = threadIdx.x & 31;
    if (gw >= kT) return;

    const float* xr = x + (size_t)gw * kD;
    float acc[kE];
#pragma unroll
    for (int e = 0; e < kE; ++e) acc[e] = 0.f;
    for (int d = lane; d < kD; d += 32) {
        float xv = xr[d];
        const float* w = rw + (size_t)d * kE;
#pragma unroll
        for (int e = 0; e < kE; ++e) acc[e] = fmaf(xv, w[e], acc[e]);
    }
#pragma unroll
    for (int e = 0; e < kE; ++e)
#pragma unroll
        for (int off = 16; off > 0; off >>= 1)
            acc[e] += __shfl_xor_sync(0xffffffffu, acc[e], off);

    if (lane == 0) {
        float lg[kE];
#pragma unroll
        for (int e = 0; e < kE; ++e) lg[e] = acc[e] + rb[e];

        int i0 = 0; float l0 = lg[0];
#pragma unroll
        for (int e = 1; e < kE; ++e) if (lg[e] > l0) { l0 = lg[e]; i0 = e; }
        int i1 = -1; float l1 = -CUDART_INF_F;
#pragma unroll
        for (int e = 0; e < kE; ++e)
            if (e != i0 && lg[e] > l1) { l1 = lg[e]; i1 = e; }

        float p[kE]; float s = 0.f;
#pragma unroll
        for (int e = 0; e < kE; ++e) { p[e] = __expf(lg[e] - l0); s += p[e]; }
        float inv = 1.f / s;
#pragma unroll
        for (int e = 0; e < kE; ++e) g_probs[gw * kE + e] = p[e] * inv;

        float r  = __expf(l1 - l0);
        float w0 = 1.f / (1.f + r);
        float w1 = r * w0;

        int s0 = atomicAdd(&g_counts[i0], 1);
        g_sid[i0 * kT + s0] = gw * 2;     g_sw[i0 * kT + s0] = w0;
        int s1 = atomicAdd(&g_counts[i1], 1);
        g_sid[i1 * kT + s1] = gw * 2 + 1; g_sw[i1 * kT + s1] = w1;
    }
}

// ---------------- kernel 2a: x -> bf16 hi/lo ----------------
__global__ void conv_x_kernel(const float* __restrict__ x) {
    size_t i = (size_t)blockIdx.x * blockDim.x + threadIdx.x;  // float4 index
    float4 v = ((const float4*)x)[i];
    float f[4] = {v.x, v.y, v.z, v.w};
    uint16_t h[4], l[4];
#pragma unroll
    for (int j = 0; j < 4; ++j) {
        __nv_bfloat16 hb = __float2bfloat16(f[j]);
        h[j] = __bfloat16_as_ushort(hb);
        l[j] = __bfloat16_as_ushort(__float2bfloat16(f[j] - __bfloat162float(hb)));
    }
    ((uint2*)g_xh)[i] = make_uint2(((uint32_t)h[1] << 16) | h[0],
                                   ((uint32_t)h[3] << 16) | h[2]);
    ((uint2*)g_xl)[i] = make_uint2(((uint32_t)l[1] << 16) | l[0],
                                   ((uint32_t)l[3] << 16) | l[2]);
}

// ---------------- kernel 2b: wgu [E][D][2F] -> [E][2F][D] bf16 hi/lo ------
// 64(d) x 32(n) tile; coalesced 128B reads AND 16B-vectorized coalesced writes.
__global__ void conv_guT_kernel(const float* __restrict__ w) {
    __shared__ float tile[64][33];   // [d][n]
    const int e = blockIdx.z, n0 = blockIdx.x * 32, d0 = blockIdx.y * 64;
    const int t = threadIdx.x;
    const int rc = t & 31, rw_ = t >> 5;
    const float* src = w + ((size_t)e * kD + d0) * (2 * kF) + n0;
#pragma unroll
    for (int i = 0; i < 8; ++i) {
        int r = rw_ + i * 8;                       // d-row 0..63
        tile[r][rc] = src[(size_t)r * (2 * kF) + rc];
    }
    __syncthreads();
    const int n = t >> 3, j = t & 7;               // n-row, 8-wide d-chunk
    uint32_t ph[4], pl[4];
#pragma unroll
    for (int q2 = 0; q2 < 4; ++q2) {
        uint16_t hh[2], ll[2];
#pragma unroll
        for (int q = 0; q < 2; ++q) {
            float v = tile[j * 8 + q2 * 2 + q][n];
            __nv_bfloat16 hb = __float2bfloat16(v);
            hh[q] = __bfloat16_as_ushort(hb);
            ll[q] = __bfloat16_as_ushort(__float2bfloat16(v - __bfloat162float(hb)));
        }
        ph[q2] = ((uint32_t)hh[1] << 16) | hh[0];
        pl[q2] = ((uint32_t)ll[1] << 16) | ll[0];
    }
    size_t o = ((size_t)e * (2 * kF) + n0 + n) * kD + d0 + j * 8;
    *(uint4*)(g_guT_h + o) = make_uint4(ph[0], ph[1], ph[2], ph[3]);
    *(uint4*)(g_guT_l + o) = make_uint4(pl[0], pl[1], pl[2], pl[3]);
}

// ---------------- kernel 2c: wdn [E][F][D] -> [E][D][F] bf16 hi/lo --------
__global__ void conv_dnT_kernel(const float* __restrict__ w) {
    __shared__ float tile[64][33];   // [f][d]
    const int e = blockIdx.z, d0 = blockIdx.x * 32, f0 = blockIdx.y * 64;
    const int t = threadIdx.x;
    const int rc = t & 31, rw_ = t >> 5;
    const float* src = w + ((size_t)e * kF + f0) * kD + d0;
#pragma unroll
    for (int i = 0; i < 8; ++i) {
        int r = rw_ + i * 8;                       // f-row 0..63
        tile[r][rc] = src[(size_t)r * kD + rc];
    }
    __syncthreads();
    const int n = t >> 3, j = t & 7;               // d-row, 8-wide f-chunk
    uint32_t ph[4], pl[4];
#pragma unroll
    for (int q2 = 0; q2 < 4; ++q2) {
        uint16_t hh[2], ll[2];
#pragma unroll
        for (int q = 0; q < 2; ++q) {
            float v = tile[j * 8 + q2 * 2 + q][n];
            __nv_bfloat16 hb = __float2bfloat16(v);
            hh[q] = __bfloat16_as_ushort(hb);
            ll[q] = __bfloat16_as_ushort(__float2bfloat16(v - __bfloat162float(hb)));
        }
        ph[q2] = ((uint32_t)hh[1] << 16) | hh[0];
        pl[q2] = ((uint32_t)ll[1] << 16) | ll[0];
    }
    size_t o = ((size_t)e * kD + d0 + n) * kF + f0 + j * 8;
    *(uint4*)(g_dnT_h + o) = make_uint4(ph[0], ph[1], ph[2], ph[3]);
    *(uint4*)(g_dnT_l + o) = make_uint4(pl[0], pl[1], pl[2], pl[3]);
}

// ---------------- kernel 3: gate_up GEMM (HMMA, bf16x3) -------------------
__global__ void __launch_bounds__(256, 1)
moe_gu_hmma(const float* __restrict__ bgu) {
    extern __shared__ char smem[];
    const int e   = blockIdx.y >> 5;
    const int m0  = (blockIdx.y & 31) * 128;
    const int cnt = g_counts[e];
    if (m0 >= cnt) return;
    const int n0 = blockIdx.x * 128;

    const uint32_t sb = s2u(smem);
    int*   s_sid  = (int*)(smem + SMS_SID);
    float* s_bias = (float*)(smem + SMS_BIAS);
    const int tid = threadIdx.x;
    if (tid < 128) {
        int m = m0 + tid;
        s_sid[tid]  = (m < cnt) ? g_sid[e * kT + m] : -1;
        s_bias[tid] = bgu[e * (2 * kF) + n0 + tid];
    }
    __syncthreads();

    const int r0 = tid >> 2, r1v = r0 + 64, ccol = tid & 3;
    int sid0 = s_sid[r0], sid1 = s_sid[r1v];
    size_t t0 = (size_t)(sid0 < 0 ? 0 : (sid0 >> 1)) * kD;
    size_t t1 = (size_t)(sid1 < 0 ? 0 : (sid1 >> 1)) * kD;
    size_t b0o = ((size_t)e * (2 * kF) + n0 + r0)  * kD;
    size_t b1o = ((size_t)e * (2 * kF) + n0 + r1v) * kD;

    float acc[4][4][4];
#pragma unroll
    for (int i = 0; i < 4; ++i)
#pragma unroll
        for (int j = 0; j < 4; ++j)
#pragma unroll
            for (int q = 0; q < 4; ++q) acc[i][j][q] = 0.f;

    run_gemm(smem, sb, tid,
             (const char*)(g_xh + t0) + ccol * 16,
             (const char*)(g_xh + t1) + ccol * 16,
             (const char*)(g_xl + t0) + ccol * 16,
             (const char*)(g_xl + t1) + ccol * 16,
             (const char*)(g_guT_h + b0o) + ccol * 16,
             (const char*)(g_guT_h + b1o) + ccol * 16,
             (const char*)(g_guT_l + b0o) + ccol * 16,
             (const char*)(g_guT_l + b1o) + ccol * 16,
             acc);

    // epilogue: bias + clamp + SiLU-GLU -> stage act hi/lo in smem (stage-0 area)
    const int wid = tid >> 5, lane = tid & 31;
    const int wm = (wid >> 2) * 64, wn = (wid & 3) * 32;
#pragma unroll
    for (int mi = 0; mi < 4; ++mi) {
        int rA = wm + mi * 16 + (lane >> 2);
        int rB = rA + 8;
#pragma unroll
        for (int ni = 0; ni < 4; ++ni) {
            int ncol = wn + ni * 8 + (lane & 3) * 2;
            float bg = s_bias[ncol], bu = s_bias[ncol + 1];
            int fl = ncol >> 1;
            float g0 = fminf(acc[mi][ni][0] + bg, kLimit);
            float u0 = fminf(fmaxf(acc[mi][ni][1] + bu, -kLimit), kLimit);
            float a0 = (u0 + 1.f) * (g0 / (1.f + __expf(-kAlpha * g0)));
            float g1 = fminf(acc[mi][ni][2] + bg, kLimit);
            float u1 = fminf(fmaxf(acc[mi][ni][3] + bu, -kLimit), kLimit);
            float a1 = (u1 + 1.f) * (g1 / (1.f + __expf(-kAlpha * g1)));
            __nv_bfloat16 h0 = __float2bfloat16(a0);
            __nv_bfloat16 l0 = __float2bfloat16(a0 - __bfloat162float(h0));
            __nv_bfloat16 h1 = __float2bfloat16(a1);
            __nv_bfloat16 l1 = __float2bfloat16(a1 - __bfloat162float(h1));
            *(__nv_bfloat16*)(smem + SMS_TILE +         rA * 128 + fl * 2) = h0;
            *(__nv_bfloat16*)(smem + SMS_TILE + 16384 + rA * 128 + fl * 2) = l0;
            *(__nv_bfloat16*)(smem + SMS_TILE +         rB * 128 + fl * 2) = h1;
            *(__nv_bfloat16*)(smem + SMS_TILE + 16384 + rB * 128 + fl * 2) = l1;
        }
    }
    __syncthreads();

    const int f0 = blockIdx.x * 64;
#pragma unroll
    for (int i = 0; i < 4; ++i) {
        int chunk = tid + i * 256;           // 1024 x 16B chunks
        int row = chunk >> 3, c8 = chunk & 7;
        int sid = s_sid[row];
        if (sid >= 0) {
            uint4 vh = *(uint4*)(smem + SMS_TILE +         row * 128 + c8 * 16);
            uint4 vl = *(uint4*)(smem + SMS_TILE + 16384 + row * 128 + c8 * 16);
            *(uint4*)(g_act_h + (size_t)sid * kF + f0 + c8 * 8) = vh;
            *(uint4*)(g_act_l + (size_t)sid * kF + f0 + c8 * 8) = vl;
        }
    }
}

// ---------------- kernel 4: down GEMM (HMMA, bf16x3) ----------------------
__global__ void __launch_bounds__(256, 1)
moe_dn_hmma(const float* __restrict__ bdn) {
    extern __shared__ char smem[];
    const int e   = blockIdx.y >> 5;
    const int m0  = (blockIdx.y & 31) * 128;
    const int cnt = g_counts[e];
    if (m0 >= cnt) return;
    const int n0 = blockIdx.x * 128;

    const uint32_t sb = s2u(smem);
    int*   s_sid  = (int*)(smem + SMS_SID);
    float* s_w    = (float*)(smem + SMS_W);
    float* s_bias = (float*)(smem + SMS_BIAS);
    const int tid = threadIdx.x;
    if (tid < 128) {
        int m = m0 + tid;
        bool v = (m < cnt);
        s_sid[tid]  = v ? g_sid[e * kT + m] : -1;
        s_w[tid]    = v ? g_sw[e * kT + m] : 0.f;
        s_bias[tid] = bdn[e * kD + n0 + tid];
    }
    __syncthreads();

    const int r0 = tid >> 2, r1v = r0 + 64, ccol = tid & 3;
    int sid0 = s_sid[r0], sid1 = s_sid[r1v];
    size_t t0 = (size_t)(sid0 < 0 ? 0 : sid0) * kF;
    size_t t1 = (size_t)(sid1 < 0 ? 0 : sid1) * kF;
    size_t b0o = ((size_t)e * kD + n0 + r0)  * kF;
    size_t b1o = ((size_t)e * kD + n0 + r1v) * kF;

    float acc[4][4][4];
#pragma unroll
    for (int i = 0; i < 4; ++i)
#pragma unroll
        for (int j = 0; j < 4; ++j)
#pragma unroll
            for (int q = 0; q < 4; ++q) acc[i][j][q] = 0.f;

    run_gemm(smem, sb, tid,
             (const char*)(g_act_h + t0) + ccol * 16,
             (const char*)(g_act_h + t1) + ccol * 16,
             (const char*)(g_act_l + t0) + ccol * 16,
             (const char*)(g_act_l + t1) + ccol * 16,
             (const char*)(g_dnT_h + b0o) + ccol * 16,
             (const char*)(g_dnT_h + b1o) + ccol * 16,
             (const char*)(g_dnT_l + b0o) + ccol * 16,
             (const char*)(g_dnT_l + b1o) + ccol * 16,
             acc);

    // epilogue: out = w_slot * (acc + bias) -> per-slot partial rows
    const int wid = tid >> 5, lane = tid & 31;
    const int wm = (wid >> 2) * 64, wn = (wid & 3) * 32;
#pragma unroll
    for (int mi = 0; mi < 4; ++mi) {
        int rA = wm + mi * 16 + (lane >> 2);
        int rB = rA + 8;
        int sidA = s_sid[rA], sidB = s_sid[rB];
        float wA = s_w[rA], wB = s_w[rB];
#pragma unroll
        for (int ni = 0; ni < 4; ++ni) {
            int ncol = wn + ni * 8 + (lane & 3) * 2;
            float b0 = s_bias[ncol], b1 = s_bias[ncol + 1];
            if (sidA >= 0) {
                float2 o = make_float2(wA * (acc[mi][ni][0] + b0),
                                       wA * (acc[mi][ni][1] + b1));
                *(float2*)(g_partial + (size_t)sidA * kD + n0 + ncol) = o;
            }
            if (sidB >= 0) {
                float2 o = make_float2(wB * (acc[mi][ni][2] + b0),
                                       wB * (acc[mi][ni][3] + b1));
                *(float2*)(g_partial + (size_t)sidB * kD + n0 + ncol) = o;
            }
        }
    }
}

// ---------------- kernel 5: combine two expert partials per token ---------
__global__ void moe_combine_kernel(float* __restrict__ out) {
    size_t idx = (size_t)blockIdx.x * blockDim.x + threadIdx.x; // float4 idx
    size_t t = idx >> 9;
    size_t c = idx & 511;
    const float4* p = (const float4*)g_partial;
    float4 a = p[(2 * t) * 512 + c];
    float4 b = p[(2 * t + 1) * 512 + c];
    ((float4*)out)[idx] = make_float4(a.x + b.x, a.y + b.y, a.z + b.z, a.w + b.w);
}

// ---------------- kernel 6: expert loads + aux loss -----------------------
__global__ void moe_loss_kernel(float* __restrict__ out_tail) {
    __shared__ float red[256];
    __shared__ float means[kE];
    float s[kE];
#pragma unroll
    for (int e = 0; e < kE; ++e) s[e] = 0.f;
    for (int t = threadIdx.x; t < kT; t += 256) {
        const float* p = g_probs + (size_t)t * kE;
#pragma unroll
        for (int e = 0; e < kE; ++e) s[e] += p[e];
    }
    for (int e = 0; e < kE; ++e) {
        red[threadIdx.x] = s[e];
        __syncthreads();
        for (int off = 128; off > 0; off >>= 1) {
            if (threadIdx.x < off) red[threadIdx.x] += red[threadIdx.x + off];
            __syncthreads();
        }
        if (threadIdx.x == 0) means[e] = red[0] / (float)kT;
        __syncthreads();
    }
    if (threadIdx.x == 0) {
        float loss = 0.f;
        for (int e = 0; e < kE; ++e) {
            float frac = (float)g_counts[e] / (float)(kT * 2);
            out_tail[e] = frac;
            loss += frac * means[e];
        }
        out_tail[kE] = kAux * (float)kE * loss;
    }
}

// ---------------- launch ----------------
extern "C" void kernel_launch(void* const* d_in, const int* in_sizes, int n_in,
                              void* d_out, int out_size) {
    const float* x   = (const float*)d_in[0];
    const float* rw  = (const float*)d_in[1];
    const float* rb  = (const float*)d_in[2];
    const float* wgu = (const float*)d_in[3];
    const float* bgu = (const float*)d_in[4];
    const float* wdn = (const float*)d_in[5];
    const float* bdn = (const float*)d_in[6];
    float* out = (float*)d_out;

    cudaFuncSetAttribute(moe_gu_hmma,
                         cudaFuncAttributeMaxDynamicSharedMemorySize, SM_TOTAL);
    cudaFuncSetAttribute(moe_dn_hmma,
                         cudaFuncAttributeMaxDynamicSharedMemorySize, SM_TOTAL);

    moe_init_kernel<<<1, 32>>>();
    moe_router_kernel<<<(kT * 32) / 256, 256>>>(x, rw, rb);

    conv_x_kernel<<<(kT * kD / 4) / 256, 256>>>(x);
    conv_guT_kernel<<<dim3(2 * kF / 32, kD / 64, kE), 256>>>(wgu);
    conv_dnT_kernel<<<dim3(kD / 32, kF / 64, kE), 256>>>(wdn);

    // worst case: one expert owns all tokens -> 32 M-tiles of 128 per expert
    moe_gu_hmma<<<dim3(2 * kF / 128, kE * 32), 256, SM_TOTAL>>>(bgu);
    moe_dn_hmma<<<dim3(kD / 128,     kE * 32), 256, SM_TOTAL>>>(bdn);

    moe_combine_kernel<<<(kT * kD / 4) / 256, 256>>>(out);
    moe_loss_kernel<<<1, 256>>>(out + (size_t)kT * kD);
}

// round 16
// speedup vs baseline: 2.8474x; 1.0000x over previous
#include <cuda_runtime.h>
#include <cuda_bf16.h>
#include <math_constants.h>
#include <cstdint>

// ---------------- problem constants ----------------
constexpr int   kD     = 2048;
constexpr int   kF     = 2048;
constexpr int   kE     = 8;
constexpr int   kT     = 4096;
constexpr int   kSlots = 2 * kT;
constexpr float kAlpha = 1.702f;
constexpr float kLimit = 7.0f;
constexpr float kAux   = 0.01f;

// smem layout for the HMMA kernels
constexpr int PITCH    = 80;            // 32 bf16 (64B) + 16B pad -> conflict-free ldmatrix
constexpr int TSZ      = 128 * PITCH;   // 10240 bytes per matrix tile
constexpr int STAGES   = 4;
constexpr int STG      = 4 * TSZ;       // bytes per stage (Ah,Al,Bh,Bl)
constexpr int SMS_SID  = 0;             // 128 ints
constexpr int SMS_W    = 512;           // 128 floats (down only)
constexpr int SMS_BIAS = 1024;          // 128 floats
constexpr int SMS_TILE = 1536;          // STAGES x [Ah,Al,Bh,Bl]
constexpr int SM_TOTAL = SMS_TILE + STAGES * STG;   // 165376

// ---------------- device scratch (no allocations allowed) ----------------
__device__ int   g_counts[kE];
__device__ int   g_sid[kE * kT];
__device__ float g_sw [kE * kT];
__device__ float g_probs[kT * kE];
__device__ __align__(16) float g_partial[(size_t)kSlots * kD];
__device__ __align__(16) __nv_bfloat16 g_xh[(size_t)kT * kD];
__device__ __align__(16) __nv_bfloat16 g_xl[(size_t)kT * kD];
__device__ __align__(16) __nv_bfloat16 g_guT_h[(size_t)kE * 2 * kF * kD];
__device__ __align__(16) __nv_bfloat16 g_guT_l[(size_t)kE * 2 * kF * kD];
__device__ __align__(16) __nv_bfloat16 g_dnT_h[(size_t)kE * kD * kF];
__device__ __align__(16) __nv_bfloat16 g_dnT_l[(size_t)kE * kD * kF];
__device__ __align__(16) __nv_bfloat16 g_act_h[(size_t)kSlots * kF];
__device__ __align__(16) __nv_bfloat16 g_act_l[(size_t)kSlots * kF];

// ---------------- PTX helpers (all base-sm_103 legal) ----------------
__device__ __forceinline__ uint32_t s2u(const void* p) {
    uint32_t a;
    asm("{ .reg .u64 t; cvta.to.shared.u64 t, %1; cvt.u32.u64 %0, t; }"
        : "=r"(a) : "l"(p));
    return a;
}
__device__ __forceinline__ void cpa(uint32_t d, const void* s) {
    asm volatile("cp.async.cg.shared.global [%0], [%1], 16;"
                 :: "r"(d), "l"(s) : "memory");
}
__device__ __forceinline__ void cp_commit() {
    asm volatile("cp.async.commit_group;" ::: "memory");
}
template <int N>
__device__ __forceinline__ void cp_wait() {
    asm volatile("cp.async.wait_group %0;" :: "n"(N) : "memory");
}
__device__ __forceinline__ void ldsm4(uint32_t a, uint32_t& r0, uint32_t& r1,
                                      uint32_t& r2, uint32_t& r3) {
    asm volatile("ldmatrix.sync.aligned.m8n8.x4.shared.b16 {%0,%1,%2,%3}, [%4];"
                 : "=r"(r0), "=r"(r1), "=r"(r2), "=r"(r3) : "r"(a));
}
__device__ __forceinline__ void mma_bf16(float* d, const uint32_t* a,
                                         uint32_t b0, uint32_t b1) {
    asm volatile(
        "mma.sync.aligned.m16n8k16.row.col.f32.bf16.bf16.f32 "
        "{%0,%1,%2,%3}, {%4,%5,%6,%7}, {%8,%9}, {%0,%1,%2,%3};"
        : "+f"(d[0]), "+f"(d[1]), "+f"(d[2]), "+f"(d[3])
        : "r"(a[0]), "r"(a[1]), "r"(a[2]), "r"(a[3]), "r"(b0), "r"(b1));
}

// ---------------- shared GEMM core: 128x128, K=2048, bf16x3 --------------
// 4-stage cp.async pipeline, BK=32, one __syncthreads per chunk.
// pX*0 pointers: row (tid>>2), pX*1: row (tid>>2)+64, both offset by (tid&3)*16B.
__device__ __forceinline__ void run_gemm(
    char* smem, uint32_t sb, int tid,
    const char* pAh0, const char* pAh1, const char* pAl0, const char* pAl1,
    const char* pBh0, const char* pBh1, const char* pBl0, const char* pBl1,
    float (*acc)[4][4])
{
    const int wid = tid >> 5, lane = tid & 31;
    const int wm = (wid >> 2) * 64, wn = (wid & 3) * 32;
    const int r0 = tid >> 2, r1v = r0 + 64, ccol = tid & 3;
    const uint32_t d0 = sb + SMS_TILE + (uint32_t)r0  * PITCH + ccol * 16;
    const uint32_t d1 = sb + SMS_TILE + (uint32_t)r1v * PITCH + ccol * 16;

    // prologue: chunks 0..2 -> stages 0..2, one commit group each
#pragma unroll
    for (int s = 0; s < 3; ++s) {
        const uint32_t st = (uint32_t)s * STG;
        const size_t  off = (size_t)s * 64;      // 32 bf16 = 64 bytes per chunk
        cpa(d0 + st + 0 * TSZ, pAh0 + off); cpa(d1 + st + 0 * TSZ, pAh1 + off);
        cpa(d0 + st + 1 * TSZ, pAl0 + off); cpa(d1 + st + 1 * TSZ, pAl1 + off);
        cpa(d0 + st + 2 * TSZ, pBh0 + off); cpa(d1 + st + 2 * TSZ, pBh1 + off);
        cpa(d0 + st + 3 * TSZ, pBl0 + off); cpa(d1 + st + 3 * TSZ, pBl1 + off);
        cp_commit();
    }

    const uint32_t lrow = lane & 15, lsel = (uint32_t)lane >> 4;
    for (int c = 0; c < 64; ++c) {
        cp_wait<2>();          // group c landed (c+1, c+2 may still be in flight)
        __syncthreads();       // all warps done with stage (c+3)&3 (read at c-1)
        {
            const int cn = c + 3;
            if (cn < 64) {
                const uint32_t st = (uint32_t)(cn & 3) * STG;
                const size_t  off = (size_t)cn * 64;
                cpa(d0 + st + 0 * TSZ, pAh0 + off); cpa(d1 + st + 0 * TSZ, pAh1 + off);
                cpa(d0 + st + 1 * TSZ, pAl0 + off); cpa(d1 + st + 1 * TSZ, pAl1 + off);
                cpa(d0 + st + 2 * TSZ, pBh0 + off); cpa(d1 + st + 2 * TSZ, pBh1 + off);
                cpa(d0 + st + 3 * TSZ, pBl0 + off); cpa(d1 + st + 3 * TSZ, pBl1 + off);
            }
            cp_commit();       // possibly empty group keeps wait-count uniform
        }
        const uint32_t base = sb + SMS_TILE + (uint32_t)(c & 3) * STG;
#pragma unroll
        for (int k16 = 0; k16 < 2; ++k16) {
            const uint32_t koff = (uint32_t)k16 * 32 + lsel * 16;
            uint32_t ah[4][4], al[4][4], bh[2][4], bl[2][4];
#pragma unroll
            for (int mi = 0; mi < 4; ++mi) {
                uint32_t a = base + (wm + mi * 16 + lrow) * PITCH + koff;
                ldsm4(a,        ah[mi][0], ah[mi][1], ah[mi][2], ah[mi][3]);
                ldsm4(a + TSZ,  al[mi][0], al[mi][1], al[mi][2], al[mi][3]);
            }
#pragma unroll
            for (int np = 0; np < 2; ++np) {
                uint32_t a = base + 2 * TSZ + (wn + np * 16 + lrow) * PITCH + koff;
                ldsm4(a,        bh[np][0], bh[np][1], bh[np][2], bh[np][3]);
                ldsm4(a + TSZ,  bl[np][0], bl[np][1], bl[np][2], bl[np][3]);
            }
#pragma unroll
            for (int mi = 0; mi < 4; ++mi)
#pragma unroll
                for (int ni = 0; ni < 4; ++ni) {
                    const int np = ni >> 1, s = ni & 1;
                    mma_bf16(acc[mi][ni], ah[mi], bh[np][s], bh[np][s + 2]);
                    mma_bf16(acc[mi][ni], ah[mi], bl[np][s], bl[np][s + 2]);
                    mma_bf16(acc[mi][ni], al[mi], bh[np][s], bh[np][s + 2]);
                }
        }
    }
}

// ---------------- kernel 0: reset counters ----------------
__global__ void moe_init_kernel() {
    if (threadIdx.x < kE) g_counts[threadIdx.x] = 0;
}

// ---------------- kernel 1: router (one warp per token) ----------------
__global__ void moe_router_kernel(const float* __restrict__ x,
                                  const float* __restrict__ rw,
                                  const float* __restrict__ rb) {
    int gw   = (blockIdx.x * blockDim.x + threadIdx.x) >> 5;
    int lane = threadIdx.x & 31;
    if (gw >= kT) return;

    const float* xr = x + (size_t)gw * kD;
    float acc[kE];
#pragma unroll
    for (int e = 0; e < kE; ++e) acc[e] = 0.f;
    for (int d = lane; d < kD; d += 32) {
        float xv = xr[d];
        const float* w = rw + (size_t)d * kE;
#pragma unroll
        for (int e = 0; e < kE; ++e) acc[e] = fmaf(xv, w[e], acc[e]);
    }
#pragma unroll
    for (int e = 0; e < kE; ++e)
#pragma unroll
        for (int off = 16; off > 0; off >>= 1)
            acc[e] += __shfl_xor_sync(0xffffffffu, acc[e], off);

    if (lane == 0) {
        float lg[kE];
#pragma unroll
        for (int e = 0; e < kE; ++e) lg[e] = acc[e] + rb[e];

        int i0 = 0; float l0 = lg[0];
#pragma unroll
        for (int e = 1; e < kE; ++e) if (lg[e] > l0) { l0 = lg[e]; i0 = e; }
        int i1 = -1; float l1 = -CUDART_INF_F;
#pragma unroll
        for (int e = 0; e < kE; ++e)
            if (e != i0 && lg[e] > l1) { l1 = lg[e]; i1 = e; }

        float p[kE]; float s = 0.f;
#pragma unroll
        for (int e = 0; e < kE; ++e) { p[e] = __expf(lg[e] - l0); s += p[e]; }
        float inv = 1.f / s;
#pragma unroll
        for (int e = 0; e < kE; ++e) g_probs[gw * kE + e] = p[e] * inv;

        float r  = __expf(l1 - l0);
        float w0 = 1.f / (1.f + r);
        float w1 = r * w0;

        int s0 = atomicAdd(&g_counts[i0], 1);
        g_sid[i0 * kT + s0] = gw * 2;     g_sw[i0 * kT + s0] = w0;
        int s1 = atomicAdd(&g_counts[i1], 1);
        g_sid[i1 * kT + s1] = gw * 2 + 1; g_sw[i1 * kT + s1] = w1;
    }
}

// ---------------- kernel 2a: x -> bf16 hi/lo ----------------
__global__ void conv_x_kernel(const float* __restrict__ x) {
    size_t i = (size_t)blockIdx.x * blockDim.x + threadIdx.x;  // float4 index
    float4 v = ((const float4*)x)[i];
    float f[4] = {v.x, v.y, v.z, v.w};
    uint16_t h[4], l[4];
#pragma unroll
    for (int j = 0; j < 4; ++j) {
        __nv_bfloat16 hb = __float2bfloat16(f[j]);
        h[j] = __bfloat16_as_ushort(hb);
        l[j] = __bfloat16_as_ushort(__float2bfloat16(f[j] - __bfloat162float(hb)));
    }
    ((uint2*)g_xh)[i] = make_uint2(((uint32_t)h[1] << 16) | h[0],
                                   ((uint32_t)h[3] << 16) | h[2]);
    ((uint2*)g_xl)[i] = make_uint2(((uint32_t)l[1] << 16) | l[0],
                                   ((uint32_t)l[3] << 16) | l[2]);
}

// ---------------- kernel 2b: wgu [E][D][2F] -> [E][2F][D] bf16 hi/lo ------
// 64(d) x 32(n) tile; coalesced 128B reads AND 16B-vectorized coalesced writes.
__global__ void conv_guT_kernel(const float* __restrict__ w) {
    __shared__ float tile[64][33];   // [d][n]
    const int e = blockIdx.z, n0 = blockIdx.x * 32, d0 = blockIdx.y * 64;
    const int t = threadIdx.x;
    const int rc = t & 31, rw_ = t >> 5;
    const float* src = w + ((size_t)e * kD + d0) * (2 * kF) + n0;
#pragma unroll
    for (int i = 0; i < 8; ++i) {
        int r = rw_ + i * 8;                       // d-row 0..63
        tile[r][rc] = src[(size_t)r * (2 * kF) + rc];
    }
    __syncthreads();
    const int n = t >> 3, j = t & 7;               // n-row, 8-wide d-chunk
    uint32_t ph[4], pl[4];
#pragma unroll
    for (int q2 = 0; q2 < 4; ++q2) {
        uint16_t hh[2], ll[2];
#pragma unroll
        for (int q = 0; q < 2; ++q) {
            float v = tile[j * 8 + q2 * 2 + q][n];
            __nv_bfloat16 hb = __float2bfloat16(v);
            hh[q] = __bfloat16_as_ushort(hb);
            ll[q] = __bfloat16_as_ushort(__float2bfloat16(v - __bfloat162float(hb)));
        }
        ph[q2] = ((uint32_t)hh[1] << 16) | hh[0];
        pl[q2] = ((uint32_t)ll[1] << 16) | ll[0];
    }
    size_t o = ((size_t)e * (2 * kF) + n0 + n) * kD + d0 + j * 8;
    *(uint4*)(g_guT_h + o) = make_uint4(ph[0], ph[1], ph[2], ph[3]);
    *(uint4*)(g_guT_l + o) = make_uint4(pl[0], pl[1], pl[2], pl[3]);
}

// ---------------- kernel 2c: wdn [E][F][D] -> [E][D][F] bf16 hi/lo --------
__global__ void conv_dnT_kernel(const float* __restrict__ w) {
    __shared__ float tile[64][33];   // [f][d]
    const int e = blockIdx.z, d0 = blockIdx.x * 32, f0 = blockIdx.y * 64;
    const int t = threadIdx.x;
    const int rc = t & 31, rw_ = t >> 5;
    const float* src = w + ((size_t)e * kF + f0) * kD + d0;
#pragma unroll
    for (int i = 0; i < 8; ++i) {
        int r = rw_ + i * 8;                       // f-row 0..63
        tile[r][rc] = src[(size_t)r * kD + rc];
    }
    __syncthreads();
    const int n = t >> 3, j = t & 7;               // d-row, 8-wide f-chunk
    uint32_t ph[4], pl[4];
#pragma unroll
    for (int q2 = 0; q2 < 4; ++q2) {
        uint16_t hh[2], ll[2];
#pragma unroll
        for (int q = 0; q < 2; ++q) {
            float v = tile[j * 8 + q2 * 2 + q][n];
            __nv_bfloat16 hb = __float2bfloat16(v);
            hh[q] = __bfloat16_as_ushort(hb);
            ll[q] = __bfloat16_as_ushort(__float2bfloat16(v - __bfloat162float(hb)));
        }
        ph[q2] = ((uint32_t)hh[1] << 16) | hh[0];
        pl[q2] = ((uint32_t)ll[1] << 16) | ll[0];
    }
    size_t o = ((size_t)e * kD + d0 + n) * kF + f0 + j * 8;
    *(uint4*)(g_dnT_h + o) = make_uint4(ph[0], ph[1], ph[2], ph[3]);
    *(uint4*)(g_dnT_l + o) = make_uint4(pl[0], pl[1], pl[2], pl[3]);
}

// ---------------- kernel 3: gate_up GEMM (HMMA, bf16x3) -------------------
__global__ void __launch_bounds__(256, 1)
moe_gu_hmma(const float* __restrict__ bgu) {
    extern __shared__ char smem[];
    const int e   = blockIdx.y >> 5;
    const int m0  = (blockIdx.y & 31) * 128;
    const int cnt = g_counts[e];
    if (m0 >= cnt) return;
    const int n0 = blockIdx.x * 128;

    const uint32_t sb = s2u(smem);
    int*   s_sid  = (int*)(smem + SMS_SID);
    float* s_bias = (float*)(smem + SMS_BIAS);
    const int tid = threadIdx.x;
    if (tid < 128) {
        int m = m0 + tid;
        s_sid[tid]  = (m < cnt) ? g_sid[e * kT + m] : -1;
        s_bias[tid] = bgu[e * (2 * kF) + n0 + tid];
    }
    __syncthreads();

    const int r0 = tid >> 2, r1v = r0 + 64, ccol = tid & 3;
    int sid0 = s_sid[r0], sid1 = s_sid[r1v];
    size_t t0 = (size_t)(sid0 < 0 ? 0 : (sid0 >> 1)) * kD;
    size_t t1 = (size_t)(sid1 < 0 ? 0 : (sid1 >> 1)) * kD;
    size_t b0o = ((size_t)e * (2 * kF) + n0 + r0)  * kD;
    size_t b1o = ((size_t)e * (2 * kF) + n0 + r1v) * kD;

    float acc[4][4][4];
#pragma unroll
    for (int i = 0; i < 4; ++i)
#pragma unroll
        for (int j = 0; j < 4; ++j)
#pragma unroll
            for (int q = 0; q < 4; ++q) acc[i][j][q] = 0.f;

    run_gemm(smem, sb, tid,
             (const char*)(g_xh + t0) + ccol * 16,
             (const char*)(g_xh + t1) + ccol * 16,
             (const char*)(g_xl + t0) + ccol * 16,
             (const char*)(g_xl + t1) + ccol * 16,
             (const char*)(g_guT_h + b0o) + ccol * 16,
             (const char*)(g_guT_h + b1o) + ccol * 16,
             (const char*)(g_guT_l + b0o) + ccol * 16,
             (const char*)(g_guT_l + b1o) + ccol * 16,
             acc);

    // epilogue: bias + clamp + SiLU-GLU -> stage act hi/lo in smem (stage-0 area)
    const int wid = tid >> 5, lane = tid & 31;
    const int wm = (wid >> 2) * 64, wn = (wid & 3) * 32;
#pragma unroll
    for (int mi = 0; mi < 4; ++mi) {
        int rA = wm + mi * 16 + (lane >> 2);
        int rB = rA + 8;
#pragma unroll
        for (int ni = 0; ni < 4; ++ni) {
            int ncol = wn + ni * 8 + (lane & 3) * 2;
            float bg = s_bias[ncol], bu = s_bias[ncol + 1];
            int fl = ncol >> 1;
            float g0 = fminf(acc[mi][ni][0] + bg, kLimit);
            float u0 = fminf(fmaxf(acc[mi][ni][1] + bu, -kLimit), kLimit);
            float a0 = (u0 + 1.f) * (g0 / (1.f + __expf(-kAlpha * g0)));
            float g1 = fminf(acc[mi][ni][2] + bg, kLimit);
            float u1 = fminf(fmaxf(acc[mi][ni][3] + bu, -kLimit), kLimit);
            float a1 = (u1 + 1.f) * (g1 / (1.f + __expf(-kAlpha * g1)));
            __nv_bfloat16 h0 = __float2bfloat16(a0);
            __nv_bfloat16 l0 = __float2bfloat16(a0 - __bfloat162float(h0));
            __nv_bfloat16 h1 = __float2bfloat16(a1);
            __nv_bfloat16 l1 = __float2bfloat16(a1 - __bfloat162float(h1));
            *(__nv_bfloat16*)(smem + SMS_TILE +         rA * 128 + fl * 2) = h0;
            *(__nv_bfloat16*)(smem + SMS_TILE + 16384 + rA * 128 + fl * 2) = l0;
            *(__nv_bfloat16*)(smem + SMS_TILE +         rB * 128 + fl * 2) = h1;
            *(__nv_bfloat16*)(smem + SMS_TILE + 16384 + rB * 128 + fl * 2) = l1;
        }
    }
    __syncthreads();

    const int f0 = blockIdx.x * 64;
#pragma unroll
    for (int i = 0; i < 4; ++i) {
        int chunk = tid + i * 256;           // 1024 x 16B chunks
        int row = chunk >> 3, c8 = chunk & 7;
        int sid = s_sid[row];
        if (sid >= 0) {
            uint4 vh = *(uint4*)(smem + SMS_TILE +         row * 128 + c8 * 16);
            uint4 vl = *(uint4*)(smem + SMS_TILE + 16384 + row * 128 + c8 * 16);
            *(uint4*)(g_act_h + (size_t)sid * kF + f0 + c8 * 8) = vh;
            *(uint4*)(g_act_l + (size_t)sid * kF + f0 + c8 * 8) = vl;
        }
    }
}

// ---------------- kernel 4: down GEMM (HMMA, bf16x3) ----------------------
__global__ void __launch_bounds__(256, 1)
moe_dn_hmma(const float* __restrict__ bdn) {
    extern __shared__ char smem[];
    const int e   = blockIdx.y >> 5;
    const int m0  = (blockIdx.y & 31) * 128;
    const int cnt = g_counts[e];
    if (m0 >= cnt) return;
    const int n0 = blockIdx.x * 128;

    const uint32_t sb = s2u(smem);
    int*   s_sid  = (int*)(smem + SMS_SID);
    float* s_w    = (float*)(smem + SMS_W);
    float* s_bias = (float*)(smem + SMS_BIAS);
    const int tid = threadIdx.x;
    if (tid < 128) {
        int m = m0 + tid;
        bool v = (m < cnt);
        s_sid[tid]  = v ? g_sid[e * kT + m] : -1;
        s_w[tid]    = v ? g_sw[e * kT + m] : 0.f;
        s_bias[tid] = bdn[e * kD + n0 + tid];
    }
    __syncthreads();

    const int r0 = tid >> 2, r1v = r0 + 64, ccol = tid & 3;
    int sid0 = s_sid[r0], sid1 = s_sid[r1v];
    size_t t0 = (size_t)(sid0 < 0 ? 0 : sid0) * kF;
    size_t t1 = (size_t)(sid1 < 0 ? 0 : sid1) * kF;
    size_t b0o = ((size_t)e * kD + n0 + r0)  * kF;
    size_t b1o = ((size_t)e * kD + n0 + r1v) * kF;

    float acc[4][4][4];
#pragma unroll
    for (int i = 0; i < 4; ++i)
#pragma unroll
        for (int j = 0; j < 4; ++j)
#pragma unroll
            for (int q = 0; q < 4; ++q) acc[i][j][q] = 0.f;

    run_gemm(smem, sb, tid,
             (const char*)(g_act_h + t0) + ccol * 16,
             (const char*)(g_act_h + t1) + ccol * 16,
             (const char*)(g_act_l + t0) + ccol * 16,
             (const char*)(g_act_l + t1) + ccol * 16,
             (const char*)(g_dnT_h + b0o) + ccol * 16,
             (const char*)(g_dnT_h + b1o) + ccol * 16,
             (const char*)(g_dnT_l + b0o) + ccol * 16,
             (const char*)(g_dnT_l + b1o) + ccol * 16,
             acc);

    // epilogue: out = w_slot * (acc + bias) -> per-slot partial rows
    const int wid = tid >> 5, lane = tid & 31;
    const int wm = (wid >> 2) * 64, wn = (wid & 3) * 32;
#pragma unroll
    for (int mi = 0; mi < 4; ++mi) {
        int rA = wm + mi * 16 + (lane >> 2);
        int rB = rA + 8;
        int sidA = s_sid[rA], sidB = s_sid[rB];
        float wA = s_w[rA], wB = s_w[rB];
#pragma unroll
        for (int ni = 0; ni < 4; ++ni) {
            int ncol = wn + ni * 8 + (lane & 3) * 2;
            float b0 = s_bias[ncol], b1 = s_bias[ncol + 1];
            if (sidA >= 0) {
                float2 o = make_float2(wA * (acc[mi][ni][0] + b0),
                                       wA * (acc[mi][ni][1] + b1));
                *(float2*)(g_partial + (size_t)sidA * kD + n0 + ncol) = o;
            }
            if (sidB >= 0) {
                float2 o = make_float2(wB * (acc[mi][ni][2] + b0),
                                       wB * (acc[mi][ni][3] + b1));
                *(float2*)(g_partial + (size_t)sidB * kD + n0 + ncol) = o;
            }
        }
    }
}

// ---------------- kernel 5: combine two expert partials per token ---------
__global__ void moe_combine_kernel(float* __restrict__ out) {
    size_t idx = (size_t)blockIdx.x * blockDim.x + threadIdx.x; // float4 idx
    size_t t = idx >> 9;
    size_t c = idx & 511;
    const float4* p = (const float4*)g_partial;
    float4 a = p[(2 * t) * 512 + c];
    float4 b = p[(2 * t + 1) * 512 + c];
    ((float4*)out)[idx] = make_float4(a.x + b.x, a.y + b.y, a.z + b.z, a.w + b.w);
}

// ---------------- kernel 6: expert loads + aux loss -----------------------
__global__ void moe_loss_kernel(float* __restrict__ out_tail) {
    __shared__ float red[256];
    __shared__ float means[kE];
    float s[kE];
#pragma unroll
    for (int e = 0; e < kE; ++e) s[e] = 0.f;
    for (int t = threadIdx.x; t < kT; t += 256) {
        const float* p = g_probs + (size_t)t * kE;
#pragma unroll
        for (int e = 0; e < kE; ++e) s[e] += p[e];
    }
    for (int e = 0; e < kE; ++e) {
        red[threadIdx.x] = s[e];
        __syncthreads();
        for (int off = 128; off > 0; off >>= 1) {
            if (threadIdx.x < off) red[threadIdx.x] += red[threadIdx.x + off];
            __syncthreads();
        }
        if (threadIdx.x == 0) means[e] = red[0] / (float)kT;
        __syncthreads();
    }
    if (threadIdx.x == 0) {
        float loss = 0.f;
        for (int e = 0; e < kE; ++e) {
            float frac = (float)g_counts[e] / (float)(kT * 2);
            out_tail[e] = frac;
            loss += frac * means[e];
        }
        out_tail[kE] = kAux * (float)kE * loss;
    }
}

// ---------------- launch ----------------
extern "C" void kernel_launch(void* const* d_in, const int* in_sizes, int n_in,
                              void* d_out, int out_size) {
    const float* x   = (const float*)d_in[0];
    const float* rw  = (const float*)d_in[1];
    const float* rb  = (const float*)d_in[2];
    const float* wgu = (const float*)d_in[3];
    const float* bgu = (const float*)d_in[4];
    const float* wdn = (const float*)d_in[5];
    const float* bdn = (const float*)d_in[6];
    float* out = (float*)d_out;

    cudaFuncSetAttribute(moe_gu_hmma,
                         cudaFuncAttributeMaxDynamicSharedMemorySize, SM_TOTAL);
    cudaFuncSetAttribute(moe_dn_hmma,
                         cudaFuncAttributeMaxDynamicSharedMemorySize, SM_TOTAL);

    moe_init_kernel<<<1, 32>>>();
    moe_router_kernel<<<(kT * 32) / 256, 256>>>(x, rw, rb);

    conv_x_kernel<<<(kT * kD / 4) / 256, 256>>>(x);
    conv_guT_kernel<<<dim3(2 * kF / 32, kD / 64, kE), 256>>>(wgu);
    conv_dnT_kernel<<<dim3(kD / 32, kF / 64, kE), 256>>>(wdn);

    // worst case: one expert owns all tokens -> 32 M-tiles of 128 per expert
    moe_gu_hmma<<<dim3(2 * kF / 128, kE * 32), 256, SM_TOTAL>>>(bgu);
    moe_dn_hmma<<<dim3(kD / 128,     kE * 32), 256, SM_TOTAL>>>(bdn);

    moe_combine_kernel<<<(kT * kD / 4) / 256, 256>>>(out);
    moe_loss_kernel<<<1, 256>>>(out + (size_t)kT * kD);
}